// round 5
// baseline (speedup 1.0000x reference)
#include <cuda_runtime.h>
#include <math.h>

// Problem constants (fixed by the reference).
#define BATCH   2
#define SEQ     4096
#define DM      768
#define NHEAD   12
#define DKH     64
#define MROWS   (BATCH * SEQ)   // 8192
#define NEGINF  (-1e9f)

// Scratch (allocation-free: __device__ globals).
__device__ float g_Q[MROWS * DM];
__device__ float g_K[MROWS * DM];
__device__ float g_V[MROWS * DM];
__device__ float g_A[MROWS * DM];

// ---------------------------------------------------------------------------
// GEMM: C[M,768] = X[M,768] @ W[768,768]^T + bias   (W stored [out,in] row-major)
// CTA tile 128x64, BK=32, 256 threads, micro-tile 8x4:
//   rows ty+16*i (i<8), cols tx+16*j (j<4).
// Smem rows padded to 36 floats so the column-operand float4 reads are at
// most 2-way bank conflicted; row-operand reads are ty-broadcast.
// Per kk-step: 128 FMA vs 12 LDS.128 per thread -> FMA-pipe-bound.
// ---------------------------------------------------------------------------
__global__ void __launch_bounds__(256) gemm_bias_kernel(
    const float* __restrict__ X, const float* __restrict__ W,
    const float* __restrict__ bias, float* __restrict__ C)
{
    __shared__ float Xs[128 * 36];
    __shared__ float Ws[64 * 36];

    const int tid = threadIdx.x;
    const int tx  = tid & 15;
    const int ty  = tid >> 4;
    const int bm0 = blockIdx.x * 128;
    const int bn0 = blockIdx.y * 64;

    float acc[8][4];
#pragma unroll
    for (int i = 0; i < 8; i++)
#pragma unroll
        for (int j = 0; j < 4; j++) acc[i][j] = 0.f;

    for (int k0 = 0; k0 < 768; k0 += 32) {
        __syncthreads();  // prior compute done reading smem
        // X tile: 128 rows x 32 k = 1024 float4 -> 4 per thread.
#pragma unroll
        for (int t = 0; t < 4; t++) {
            const int id = tid + t * 256;
            const int r  = id >> 3;          // 0..127
            const int kq = (id & 7) << 2;    // 0,4,...,28
            const float4 v = *(const float4*)&X[(size_t)(bm0 + r) * DM + k0 + kq];
            *(float4*)&Xs[r * 36 + kq] = v;
        }
        // W tile: 64 rows x 32 k = 512 float4 -> 2 per thread.
#pragma unroll
        for (int t = 0; t < 2; t++) {
            const int id = tid + t * 256;
            const int r  = id >> 3;          // 0..63
            const int kq = (id & 7) << 2;
            const float4 v = *(const float4*)&W[(size_t)(bn0 + r) * DM + k0 + kq];
            *(float4*)&Ws[r * 36 + kq] = v;
        }
        __syncthreads();

#pragma unroll
        for (int kk = 0; kk < 32; kk += 4) {
            float4 b[4];
#pragma unroll
            for (int j = 0; j < 4; j++) b[j] = *(const float4*)&Ws[(tx + 16 * j) * 36 + kk];
#pragma unroll
            for (int i = 0; i < 8; i++) {
                const float4 a = *(const float4*)&Xs[(ty + 16 * i) * 36 + kk];
#pragma unroll
                for (int j = 0; j < 4; j++) {
                    acc[i][j] += a.x * b[j].x;
                    acc[i][j] += a.y * b[j].y;
                    acc[i][j] += a.z * b[j].z;
                    acc[i][j] += a.w * b[j].w;
                }
            }
        }
    }

#pragma unroll
    for (int i = 0; i < 8; i++) {
        const int row = bm0 + ty + 16 * i;
#pragma unroll
        for (int j = 0; j < 4; j++) {
            const int col = bn0 + tx + 16 * j;
            C[(size_t)row * DM + col] = acc[i][j] + bias[col];
        }
    }
}

// ---------------------------------------------------------------------------
// Flash attention, fp32, causal + key-padding mask, online softmax.
// Grid: (S/64, NHEAD, BATCH). Block 256.
// Dyn smem: Qs[64*64] | KP[64*68] (K tile, later aliased for P) | Vs[64*64]
// ---------------------------------------------------------------------------
#define ATTN_SMEM_FLOATS (64 * 64 + 64 * 68 + 64 * 64)
#define ATTN_SMEM_BYTES  (ATTN_SMEM_FLOATS * 4)

__global__ void __launch_bounds__(256) attn_kernel(const int* __restrict__ mask)
{
    extern __shared__ float sm[];
    float* Qs = sm;                 // [64][64]
    float* KP = sm + 64 * 64;       // [64][68]  K tile, then P tile
    float* Vs = KP + 64 * 68;       // [64][64]

    const int tid = threadIdx.x;
    const int tx  = tid & 15;
    const int ty  = tid >> 4;
    const int qt  = blockIdx.x;
    const int h   = blockIdx.y;
    const int b   = blockIdx.z;
    const int q0  = qt * 64;
    const size_t rowbase = (size_t)b * SEQ;

    // Load Q tile (stride 64; compute reads are ty-broadcast so no padding).
#pragma unroll
    for (int t = 0; t < 4; t++) {
        const int id = tid + t * 256;
        const int r  = id >> 4;
        const int dq = (id & 15) << 2;
        const float4 v = *(const float4*)&g_Q[(rowbase + q0 + r) * DM + h * DKH + dq];
        *(float4*)&Qs[r * 64 + dq] = v;
    }

    float O[4][4];
    float mrow[4], lrow[4];
#pragma unroll
    for (int i = 0; i < 4; i++) {
        mrow[i] = -INFINITY;
        lrow[i] = 0.f;
#pragma unroll
        for (int j = 0; j < 4; j++) O[i][j] = 0.f;
    }

    for (int kt = 0; kt <= qt; kt++) {
        const int k0 = kt * 64;
        __syncthreads();  // previous iteration done reading KP/Vs (also orders Q load)
#pragma unroll
        for (int t = 0; t < 4; t++) {
            const int id = tid + t * 256;
            const int r  = id >> 4;
            const int dq = (id & 15) << 2;
            const float4 kv = *(const float4*)&g_K[(rowbase + k0 + r) * DM + h * DKH + dq];
            *(float4*)&KP[r * 68 + dq] = kv;
            const float4 vv = *(const float4*)&g_V[(rowbase + k0 + r) * DM + h * DKH + dq];
            *(float4*)&Vs[r * 64 + dq] = vv;
        }
        __syncthreads();

        // Key padding mask for this thread's 4 columns.
        int mk[4];
#pragma unroll
        for (int j = 0; j < 4; j++) mk[j] = mask[b * SEQ + k0 + tx + 16 * j];

        // S = Q @ K^T (micro-tile), d vectorized by 4.
        float s[4][4];
#pragma unroll
        for (int i = 0; i < 4; i++)
#pragma unroll
            for (int j = 0; j < 4; j++) s[i][j] = 0.f;

#pragma unroll
        for (int d = 0; d < 64; d += 4) {
            float4 qv[4], kv[4];
#pragma unroll
            for (int i = 0; i < 4; i++) qv[i] = *(const float4*)&Qs[(ty + 16 * i) * 64 + d];
#pragma unroll
            for (int j = 0; j < 4; j++) kv[j] = *(const float4*)&KP[(tx + 16 * j) * 68 + d];
#pragma unroll
            for (int i = 0; i < 4; i++)
#pragma unroll
                for (int j = 0; j < 4; j++) {
                    s[i][j] += qv[i].x * kv[j].x;
                    s[i][j] += qv[i].y * kv[j].y;
                    s[i][j] += qv[i].z * kv[j].z;
                    s[i][j] += qv[i].w * kv[j].w;
                }
        }

        // Scale + masks.
        const bool diag = (kt == qt);
#pragma unroll
        for (int i = 0; i < 4; i++) {
            const int qg = q0 + ty + 16 * i;
#pragma unroll
            for (int j = 0; j < 4; j++) {
                float v = s[i][j] * 0.125f;   // 1/sqrt(64)
                const int kg = k0 + tx + 16 * j;
                if (mk[j] == 0) v = NEGINF;
                if (diag && kg > qg) v = NEGINF;
                s[i][j] = v;
            }
        }

        // Online softmax update. Row r = ty+16i is owned by the 16 lanes with
        // the same ty (consecutive lanes) -> shfl_xor width 16.
#pragma unroll
        for (int i = 0; i < 4; i++) {
            float rm = fmaxf(fmaxf(s[i][0], s[i][1]), fmaxf(s[i][2], s[i][3]));
#pragma unroll
            for (int off = 8; off >= 1; off >>= 1)
                rm = fmaxf(rm, __shfl_xor_sync(0xffffffffu, rm, off, 16));
            const float mn   = fmaxf(mrow[i], rm);
            const float corr = __expf(mrow[i] - mn);
            float rs = 0.f;
#pragma unroll
            for (int j = 0; j < 4; j++) {
                s[i][j] = __expf(s[i][j] - mn);
                rs += s[i][j];
            }
#pragma unroll
            for (int off = 8; off >= 1; off >>= 1)
                rs += __shfl_xor_sync(0xffffffffu, rs, off, 16);
            lrow[i] = lrow[i] * corr + rs;
#pragma unroll
            for (int j = 0; j < 4; j++) O[i][j] *= corr;
            mrow[i] = mn;
        }

        __syncthreads();  // everyone done reading K from KP
        // Write P into the K buffer (row-major [q-row][k-col], stride 68).
#pragma unroll
        for (int i = 0; i < 4; i++)
#pragma unroll
            for (int j = 0; j < 4; j++)
                KP[(ty + 16 * i) * 68 + tx + 16 * j] = s[i][j];
        __syncthreads();

        // O += P @ V, kk vectorized by 4 (P reads ty-broadcast float4,
        // V reads lane-contiguous scalars, half-warp broadcast).
#pragma unroll
        for (int kk = 0; kk < 64; kk += 4) {
            float4 pv[4];
#pragma unroll
            for (int i = 0; i < 4; i++) pv[i] = *(const float4*)&KP[(ty + 16 * i) * 68 + kk];
#pragma unroll
            for (int q = 0; q < 4; q++) {
                float pA[4];
#pragma unroll
                for (int i = 0; i < 4; i++) {
                    const float4 t = pv[i];
                    pA[i] = (q == 0) ? t.x : (q == 1) ? t.y : (q == 2) ? t.z : t.w;
                }
                float vv[4];
#pragma unroll
                for (int j = 0; j < 4; j++) vv[j] = Vs[(kk + q) * 64 + tx + 16 * j];
#pragma unroll
                for (int i = 0; i < 4; i++)
#pragma unroll
                    for (int j = 0; j < 4; j++) O[i][j] += pA[i] * vv[j];
            }
        }
    }

    // Epilogue: normalize and write the per-head column slice of g_A.
#pragma unroll
    for (int i = 0; i < 4; i++) {
        const float inv = 1.f / lrow[i];
        const size_t row = rowbase + q0 + ty + 16 * i;
#pragma unroll
        for (int j = 0; j < 4; j++)
            g_A[row * DM + h * DKH + tx + 16 * j] = O[i][j] * inv;
    }
}

// ---------------------------------------------------------------------------
// Launch
// ---------------------------------------------------------------------------
extern "C" void kernel_launch(void* const* d_in, const int* in_sizes, int n_in,
                              void* d_out, int out_size)
{
    const float* query = (const float*)d_in[0];
    const float* key   = (const float*)d_in[1];
    const float* value = (const float*)d_in[2];
    const int*   mask  = (const int*)  d_in[3];
    const float* Wq    = (const float*)d_in[4];
    const float* bq    = (const float*)d_in[5];
    const float* Wk    = (const float*)d_in[6];
    const float* bk    = (const float*)d_in[7];
    const float* Wv    = (const float*)d_in[8];
    const float* bv    = (const float*)d_in[9];
    const float* Wo    = (const float*)d_in[10];
    const float* bo    = (const float*)d_in[11];
    float* out = (float*)d_out;

    float *Qb, *Kb, *Vb, *Ab;
    cudaGetSymbolAddress((void**)&Qb, g_Q);
    cudaGetSymbolAddress((void**)&Kb, g_K);
    cudaGetSymbolAddress((void**)&Vb, g_V);
    cudaGetSymbolAddress((void**)&Ab, g_A);

    cudaFuncSetAttribute(attn_kernel,
                         cudaFuncAttributeMaxDynamicSharedMemorySize,
                         ATTN_SMEM_BYTES);

    const dim3 ggrid(MROWS / 128, DM / 64);   // (64, 12)
    gemm_bias_kernel<<<ggrid, 256>>>(query, Wq, bq, Qb);
    gemm_bias_kernel<<<ggrid, 256>>>(key,   Wk, bk, Kb);
    gemm_bias_kernel<<<ggrid, 256>>>(value, Wv, bv, Vb);

    attn_kernel<<<dim3(SEQ / 64, NHEAD, BATCH), 256, ATTN_SMEM_BYTES>>>(mask);

    gemm_bias_kernel<<<ggrid, 256>>>(Ab, Wo, bo, out);
}

// round 7
// speedup vs baseline: 1.2532x; 1.2532x over previous
#include <cuda_runtime.h>
#include <cuda_fp16.h>
#include <math.h>
#include <stdint.h>

// Problem constants (fixed by the reference).
#define BATCH   2
#define SEQ     4096
#define DM      768
#define NHEAD   12
#define DKH     64
#define MROWS   (BATCH * SEQ)   // 8192
#define KCAT    (3 * DM)        // 2304: [hi | lo | hi] x [hi | hi | lo]
#define NEGINF  (-1e9f)

// Scratch (allocation-free: __device__ globals).
__device__ float g_Q[MROWS * DM];
__device__ float g_K[MROWS * DM];
__device__ float g_V[MROWS * DM];
__device__ float g_A[MROWS * DM];
__device__ __half g_Xcat[(size_t)MROWS * KCAT];  // 37.7 MB
__device__ __half g_Wcat[(size_t)DM * KCAT];     // 3.5 MB

// ===========================================================================
// Warp-MMA helpers (sm_80+ path, legal on plain sm_103)
// ===========================================================================
__device__ __forceinline__ uint32_t smem_u32(const void* p) {
    uint32_t a;
    asm("{ .reg .u64 t; cvta.to.shared.u64 t, %1; cvt.u32.u64 %0, t; }"
        : "=r"(a) : "l"(p));
    return a;
}
__device__ __forceinline__ void ldsm4(uint32_t* r, uint32_t addr) {
    asm volatile("ldmatrix.sync.aligned.m8n8.x4.shared.b16 {%0,%1,%2,%3}, [%4];"
                 : "=r"(r[0]), "=r"(r[1]), "=r"(r[2]), "=r"(r[3]) : "r"(addr));
}
__device__ __forceinline__ void mma16816(float* c, const uint32_t* a,
                                         uint32_t b0, uint32_t b1) {
    asm volatile(
        "mma.sync.aligned.m16n8k16.row.col.f32.f16.f16.f32 "
        "{%0,%1,%2,%3}, {%4,%5,%6,%7}, {%8,%9}, {%0,%1,%2,%3};"
        : "+f"(c[0]), "+f"(c[1]), "+f"(c[2]), "+f"(c[3])
        : "r"(a[0]), "r"(a[1]), "r"(a[2]), "r"(a[3]), "r"(b0), "r"(b1));
}
__device__ __forceinline__ void cp16(uint32_t dst, const void* src) {
    asm volatile("cp.async.cg.shared.global [%0], [%1], 16;"
                 :: "r"(dst), "l"(src));
}
#define CP_COMMIT() asm volatile("cp.async.commit_group;" ::: "memory")
#define CP_WAIT(n)  asm volatile("cp.async.wait_group %0;" :: "n"(n) : "memory")

// ===========================================================================
// Split conversion: fp32 [rows x 768] -> fp16 [rows x 2304]
// xmode=1: [hi | lo | hi]   (activations)
// xmode=0: [hi | hi | lo]   (weights)
// Product over K=2304 = XhiWhi + XloWhi + XhiWlo  (drops O(2^-22) XloWlo).
// ===========================================================================
__global__ void __launch_bounds__(256) conv_split_kernel(
    const float* __restrict__ in, __half* __restrict__ out,
    int rows, int xmode)
{
    const int t = blockIdx.x * 256 + threadIdx.x;
    const int total = rows * (DM / 4);
    if (t >= total) return;
    const int r  = t / (DM / 4);
    const int c4 = (t - r * (DM / 4)) * 4;
    const float4 v = *(const float4*)&in[(size_t)r * DM + c4];

    __half2 h01 = __float22half2_rn(make_float2(v.x, v.y));
    __half2 h23 = __float22half2_rn(make_float2(v.z, v.w));
    float2 hf01 = __half22float2(h01);
    float2 hf23 = __half22float2(h23);
    __half2 l01 = __float22half2_rn(make_float2(v.x - hf01.x, v.y - hf01.y));
    __half2 l23 = __float22half2_rn(make_float2(v.z - hf23.x, v.w - hf23.y));

    uint2 hi, lo;
    hi.x = *(uint32_t*)&h01; hi.y = *(uint32_t*)&h23;
    lo.x = *(uint32_t*)&l01; lo.y = *(uint32_t*)&l23;

    __half* orow = out + (size_t)r * KCAT;
    *(uint2*)&orow[c4]            = hi;
    *(uint2*)&orow[DM + c4]       = xmode ? lo : hi;
    *(uint2*)&orow[2 * DM + c4]   = xmode ? hi : lo;
}

// ===========================================================================
// Tensor-core GEMM: C[M,768] = Xcat[M,2304] . Wcat[768,2304]^T + bias (fp32 out)
// CTA 128x128, 8 warps (warp tile 64x32), BK=64, double-buffered cp.async.
// Smem tiles padded to stride 72 halves (144 B rows: 16B-aligned,
// conflict-free ldmatrix).
// ===========================================================================
#define BKC       64
#define SM_STR    72                         // halves per smem row
#define TILE_B    (128 * SM_STR * 2)         // 18432 B per tile
#define GS_TOTAL  (4 * TILE_B)               // 73728 B (A0,A1,B0,B1)
#define NCHUNK    (KCAT / BKC)               // 36

__global__ void __launch_bounds__(256)
tc_gemm_kernel(const __half* __restrict__ Xc,
               const __half* __restrict__ Wc,
               const float* __restrict__ bias,
               float* __restrict__ C)
{
    extern __shared__ char smem[];
    const uint32_t sbase = smem_u32(smem);
    const uint32_t aBuf[2] = { sbase,              sbase + TILE_B };
    const uint32_t bBuf[2] = { sbase + 2 * TILE_B, sbase + 3 * TILE_B };

    const int tid = threadIdx.x;
    const int wid = tid >> 5;
    const int L   = tid & 31;
    const int wm  = wid & 1;        // m half (64 rows)
    const int wn  = wid >> 1;       // n quarter (32 cols)
    const int bm0 = blockIdx.x * 128;
    const int bn0 = blockIdx.y * 128;

    // ldmatrix per-lane address components.
    const int aRow = (L & 7) + ((L >> 3) & 1) * 8;
    const int aK   = ((L >> 4) & 1) * 8;
    const int bRow = (L & 7) + ((L >> 4) & 1) * 8;
    const int bK   = ((L >> 3) & 1) * 8;
    const uint32_t aOff = ((wm * 64 + aRow) * SM_STR + aK) * 2;
    const uint32_t bOff = ((wn * 32 + bRow) * SM_STR + bK) * 2;

    // Global-load mapping: 8 x 16B per thread per chunk (A:4, B:4).
    const int gr  = tid >> 1;                 // 0..127 (row), 2 threads/row
    const int gc8 = (tid & 1) * 32;           // halves 0 or 32
    // each thread does 4 contiguous 16B (= 8 halves) units starting at gc8? No:
    // simpler: u = tid + t*256, r = u>>3, c8 = (u&7)*8  (4 iterations)
    (void)gr; (void)gc8;

    float acc[4][4][4];
#pragma unroll
    for (int mt = 0; mt < 4; mt++)
#pragma unroll
        for (int nt = 0; nt < 4; nt++)
#pragma unroll
            for (int i = 0; i < 4; i++) acc[mt][nt][i] = 0.f;

    // Chunk loader.
    auto issue = [&](int c) {
        const int buf = c & 1;
#pragma unroll
        for (int t = 0; t < 4; t++) {
            const int u  = tid + t * 256;     // 0..1023
            const int r  = u >> 3;            // 0..127
            const int c8 = (u & 7) * 8;       // half index 0..56
            cp16(aBuf[buf] + (r * SM_STR + c8) * 2,
                 &Xc[(size_t)(bm0 + r) * KCAT + c * BKC + c8]);
            cp16(bBuf[buf] + (r * SM_STR + c8) * 2,
                 &Wc[(size_t)(bn0 + r) * KCAT + c * BKC + c8]);
        }
        CP_COMMIT();
    };

    issue(0);

    for (int c = 0; c < NCHUNK; ++c) {
        const int buf = c & 1;
        if (c + 1 < NCHUNK) {
            issue(c + 1);
            CP_WAIT(1);           // chunk c resident
        } else {
            CP_WAIT(0);
        }
        __syncthreads();

#pragma unroll
        for (int ks = 0; ks < 4; ++ks) {
            uint32_t af[4][4];
#pragma unroll
            for (int mt = 0; mt < 4; mt++)
                ldsm4(af[mt], aBuf[buf] + aOff + (mt * 16 * SM_STR + ks * 16) * 2);
            uint32_t bf[2][4];
#pragma unroll
            for (int np = 0; np < 2; np++)
                ldsm4(bf[np], bBuf[buf] + bOff + (np * 16 * SM_STR + ks * 16) * 2);
#pragma unroll
            for (int mt = 0; mt < 4; mt++)
#pragma unroll
                for (int nt = 0; nt < 4; nt++)
                    mma16816(acc[mt][nt], af[mt],
                             bf[nt >> 1][(nt & 1) * 2],
                             bf[nt >> 1][(nt & 1) * 2 + 1]);
        }
        __syncthreads();          // mma done before buf is overwritten
    }

    // Epilogue: add bias, store fp32.
    const int qr = L >> 2;
    const int qc = (L & 3) * 2;
#pragma unroll
    for (int mt = 0; mt < 4; mt++) {
        const int row0 = bm0 + wm * 64 + mt * 16 + qr;
#pragma unroll
        for (int nt = 0; nt < 4; nt++) {
            const int col = bn0 + wn * 32 + nt * 8 + qc;
            const float2 bv = *(const float2*)&bias[col];
            const float* cc = acc[mt][nt];
            float2 o0 = make_float2(cc[0] + bv.x, cc[1] + bv.y);
            float2 o1 = make_float2(cc[2] + bv.x, cc[3] + bv.y);
            *(float2*)&C[(size_t)row0 * DM + col]       = o0;
            *(float2*)&C[(size_t)(row0 + 8) * DM + col] = o1;
        }
    }
}

// ===========================================================================
// Flash attention, fp32, causal + key-padding mask, online softmax.
// (unchanged from the passing R4 kernel)
// ===========================================================================
#define ATTN_SMEM_FLOATS (64 * 64 + 64 * 68 + 64 * 64)
#define ATTN_SMEM_BYTES  (ATTN_SMEM_FLOATS * 4)

__global__ void __launch_bounds__(256) attn_kernel(const int* __restrict__ mask)
{
    extern __shared__ float sm[];
    float* Qs = sm;                 // [64][64]
    float* KP = sm + 64 * 64;       // [64][68]  K tile, then P tile
    float* Vs = KP + 64 * 68;       // [64][64]

    const int tid = threadIdx.x;
    const int tx  = tid & 15;
    const int ty  = tid >> 4;
    const int qt  = blockIdx.x;
    const int h   = blockIdx.y;
    const int b   = blockIdx.z;
    const int q0  = qt * 64;
    const size_t rowbase = (size_t)b * SEQ;

#pragma unroll
    for (int t = 0; t < 4; t++) {
        const int id = tid + t * 256;
        const int r  = id >> 4;
        const int dq = (id & 15) << 2;
        const float4 v = *(const float4*)&g_Q[(rowbase + q0 + r) * DM + h * DKH + dq];
        *(float4*)&Qs[r * 64 + dq] = v;
    }

    float O[4][4];
    float mrow[4], lrow[4];
#pragma unroll
    for (int i = 0; i < 4; i++) {
        mrow[i] = -INFINITY;
        lrow[i] = 0.f;
#pragma unroll
        for (int j = 0; j < 4; j++) O[i][j] = 0.f;
    }

    for (int kt = 0; kt <= qt; kt++) {
        const int k0 = kt * 64;
        __syncthreads();
#pragma unroll
        for (int t = 0; t < 4; t++) {
            const int id = tid + t * 256;
            const int r  = id >> 4;
            const int dq = (id & 15) << 2;
            const float4 kv = *(const float4*)&g_K[(rowbase + k0 + r) * DM + h * DKH + dq];
            *(float4*)&KP[r * 68 + dq] = kv;
            const float4 vv = *(const float4*)&g_V[(rowbase + k0 + r) * DM + h * DKH + dq];
            *(float4*)&Vs[r * 64 + dq] = vv;
        }
        __syncthreads();

        int mk[4];
#pragma unroll
        for (int j = 0; j < 4; j++) mk[j] = mask[b * SEQ + k0 + tx + 16 * j];

        float s[4][4];
#pragma unroll
        for (int i = 0; i < 4; i++)
#pragma unroll
            for (int j = 0; j < 4; j++) s[i][j] = 0.f;

#pragma unroll
        for (int d = 0; d < 64; d += 4) {
            float4 qv[4], kv[4];
#pragma unroll
            for (int i = 0; i < 4; i++) qv[i] = *(const float4*)&Qs[(ty + 16 * i) * 64 + d];
#pragma unroll
            for (int j = 0; j < 4; j++) kv[j] = *(const float4*)&KP[(tx + 16 * j) * 68 + d];
#pragma unroll
            for (int i = 0; i < 4; i++)
#pragma unroll
                for (int j = 0; j < 4; j++) {
                    s[i][j] += qv[i].x * kv[j].x;
                    s[i][j] += qv[i].y * kv[j].y;
                    s[i][j] += qv[i].z * kv[j].z;
                    s[i][j] += qv[i].w * kv[j].w;
                }
        }

        const bool diag = (kt == qt);
#pragma unroll
        for (int i = 0; i < 4; i++) {
            const int qg = q0 + ty + 16 * i;
#pragma unroll
            for (int j = 0; j < 4; j++) {
                float v = s[i][j] * 0.125f;
                const int kg = k0 + tx + 16 * j;
                if (mk[j] == 0) v = NEGINF;
                if (diag && kg > qg) v = NEGINF;
                s[i][j] = v;
            }
        }

#pragma unroll
        for (int i = 0; i < 4; i++) {
            float rm = fmaxf(fmaxf(s[i][0], s[i][1]), fmaxf(s[i][2], s[i][3]));
#pragma unroll
            for (int off = 8; off >= 1; off >>= 1)
                rm = fmaxf(rm, __shfl_xor_sync(0xffffffffu, rm, off, 16));
            const float mn   = fmaxf(mrow[i], rm);
            const float corr = __expf(mrow[i] - mn);
            float rs = 0.f;
#pragma unroll
            for (int j = 0; j < 4; j++) {
                s[i][j] = __expf(s[i][j] - mn);
                rs += s[i][j];
            }
#pragma unroll
            for (int off = 8; off >= 1; off >>= 1)
                rs += __shfl_xor_sync(0xffffffffu, rs, off, 16);
            lrow[i] = lrow[i] * corr + rs;
#pragma unroll
            for (int j = 0; j < 4; j++) O[i][j] *= corr;
            mrow[i] = mn;
        }

        __syncthreads();
#pragma unroll
        for (int i = 0; i < 4; i++)
#pragma unroll
            for (int j = 0; j < 4; j++)
                KP[(ty + 16 * i) * 68 + tx + 16 * j] = s[i][j];
        __syncthreads();

#pragma unroll
        for (int kk = 0; kk < 64; kk += 4) {
            float4 pv[4];
#pragma unroll
            for (int i = 0; i < 4; i++) pv[i] = *(const float4*)&KP[(ty + 16 * i) * 68 + kk];
#pragma unroll
            for (int q = 0; q < 4; q++) {
                float pA[4];
#pragma unroll
                for (int i = 0; i < 4; i++) {
                    const float4 t = pv[i];
                    pA[i] = (q == 0) ? t.x : (q == 1) ? t.y : (q == 2) ? t.z : t.w;
                }
                float vv[4];
#pragma unroll
                for (int j = 0; j < 4; j++) vv[j] = Vs[(kk + q) * 64 + tx + 16 * j];
#pragma unroll
                for (int i = 0; i < 4; i++)
#pragma unroll
                    for (int j = 0; j < 4; j++) O[i][j] += pA[i] * vv[j];
            }
        }
    }

#pragma unroll
    for (int i = 0; i < 4; i++) {
        const float inv = 1.f / lrow[i];
        const size_t row = rowbase + q0 + ty + 16 * i;
#pragma unroll
        for (int j = 0; j < 4; j++)
            g_A[row * DM + h * DKH + tx + 16 * j] = O[i][j] * inv;
    }
}

// ===========================================================================
// Launch
// ===========================================================================
extern "C" void kernel_launch(void* const* d_in, const int* in_sizes, int n_in,
                              void* d_out, int out_size)
{
    const float* query = (const float*)d_in[0];
    const float* key   = (const float*)d_in[1];
    const float* value = (const float*)d_in[2];
    const int*   mask  = (const int*)  d_in[3];
    const float* Wq    = (const float*)d_in[4];
    const float* bq    = (const float*)d_in[5];
    const float* Wk    = (const float*)d_in[6];
    const float* bk    = (const float*)d_in[7];
    const float* Wv    = (const float*)d_in[8];
    const float* bv    = (const float*)d_in[9];
    const float* Wo    = (const float*)d_in[10];
    const float* bo    = (const float*)d_in[11];
    float* out = (float*)d_out;

    float *Qb, *Kb, *Vb, *Ab;
    __half *Xcat, *Wcat;
    cudaGetSymbolAddress((void**)&Qb, g_Q);
    cudaGetSymbolAddress((void**)&Kb, g_K);
    cudaGetSymbolAddress((void**)&Vb, g_V);
    cudaGetSymbolAddress((void**)&Ab, g_A);
    cudaGetSymbolAddress((void**)&Xcat, g_Xcat);
    cudaGetSymbolAddress((void**)&Wcat, g_Wcat);

    cudaFuncSetAttribute(attn_kernel,
                         cudaFuncAttributeMaxDynamicSharedMemorySize,
                         ATTN_SMEM_BYTES);
    cudaFuncSetAttribute(tc_gemm_kernel,
                         cudaFuncAttributeMaxDynamicSharedMemorySize,
                         GS_TOTAL);

    const int convX_blocks = (MROWS * (DM / 4) + 255) / 256;  // 6144
    const int convW_blocks = (DM * (DM / 4) + 255) / 256;     // 576
    const dim3 ggrid(MROWS / 128, DM / 128);                  // (64, 6)

    // Q projection
    conv_split_kernel<<<convX_blocks, 256>>>(query, Xcat, MROWS, 1);
    conv_split_kernel<<<convW_blocks, 256>>>(Wq, Wcat, DM, 0);
    tc_gemm_kernel<<<ggrid, 256, GS_TOTAL>>>(Xcat, Wcat, bq, Qb);
    // K projection
    conv_split_kernel<<<convX_blocks, 256>>>(key, Xcat, MROWS, 1);
    conv_split_kernel<<<convW_blocks, 256>>>(Wk, Wcat, DM, 0);
    tc_gemm_kernel<<<ggrid, 256, GS_TOTAL>>>(Xcat, Wcat, bk, Kb);
    // V projection
    conv_split_kernel<<<convX_blocks, 256>>>(value, Xcat, MROWS, 1);
    conv_split_kernel<<<convW_blocks, 256>>>(Wv, Wcat, DM, 0);
    tc_gemm_kernel<<<ggrid, 256, GS_TOTAL>>>(Xcat, Wcat, bv, Vb);

    // Attention (fp32 SIMT, unchanged)
    attn_kernel<<<dim3(SEQ / 64, NHEAD, BATCH), 256, ATTN_SMEM_BYTES>>>(mask);

    // Output projection
    conv_split_kernel<<<convX_blocks, 256>>>(Ab, Xcat, MROWS, 1);
    conv_split_kernel<<<convW_blocks, 256>>>(Wo, Wcat, DM, 0);
    tc_gemm_kernel<<<ggrid, 256, GS_TOTAL>>>(Xcat, Wcat, bo, out);
}

// round 8
// speedup vs baseline: 2.3606x; 1.8837x over previous
#include <cuda_runtime.h>
#include <cuda_fp16.h>
#include <math.h>
#include <stdint.h>

// Problem constants (fixed by the reference).
#define BATCH   2
#define SEQ     4096
#define DM      768
#define NHEAD   12
#define DKH     64
#define MROWS   (BATCH * SEQ)   // 8192
#define KCAT    (3 * DM)        // 2304: [hi | lo | hi] x [hi | hi | lo]
#define DC      192             // concat head dim for QK split
#define NEGINF  (-1e9f)

// Scratch (allocation-free: __device__ globals).
__device__ float g_Q[MROWS * DM];
__device__ float g_K[MROWS * DM];
__device__ float g_V[MROWS * DM];
__device__ float g_A[MROWS * DM];
__device__ __half g_Xcat[(size_t)MROWS * KCAT];            // 37.7 MB
__device__ __half g_Wcat[(size_t)DM * KCAT];               // 3.5 MB
__device__ __half g_Qc[(size_t)BATCH * NHEAD * SEQ * DC];  // 37.7 MB
__device__ __half g_Kc[(size_t)BATCH * NHEAD * SEQ * DC];  // 37.7 MB
__device__ __half g_Vt[(size_t)BATCH * NHEAD * 128 * SEQ]; // 25.2 MB (hi rows 0-63, lo 64-127)

// ===========================================================================
// Warp-MMA helpers (sm_80+ path, legal on plain sm_103)
// ===========================================================================
__device__ __forceinline__ uint32_t smem_u32(const void* p) {
    uint32_t a;
    asm("{ .reg .u64 t; cvta.to.shared.u64 t, %1; cvt.u32.u64 %0, t; }"
        : "=r"(a) : "l"(p));
    return a;
}
__device__ __forceinline__ void ldsm4(uint32_t* r, uint32_t addr) {
    asm volatile("ldmatrix.sync.aligned.m8n8.x4.shared.b16 {%0,%1,%2,%3}, [%4];"
                 : "=r"(r[0]), "=r"(r[1]), "=r"(r[2]), "=r"(r[3]) : "r"(addr));
}
__device__ __forceinline__ void mma16816(float* c, const uint32_t* a,
                                         uint32_t b0, uint32_t b1) {
    asm volatile(
        "mma.sync.aligned.m16n8k16.row.col.f32.f16.f16.f32 "
        "{%0,%1,%2,%3}, {%4,%5,%6,%7}, {%8,%9}, {%0,%1,%2,%3};"
        : "+f"(c[0]), "+f"(c[1]), "+f"(c[2]), "+f"(c[3])
        : "r"(a[0]), "r"(a[1]), "r"(a[2]), "r"(a[3]), "r"(b0), "r"(b1));
}
__device__ __forceinline__ void cp16(uint32_t dst, const void* src) {
    asm volatile("cp.async.cg.shared.global [%0], [%1], 16;"
                 :: "r"(dst), "l"(src));
}
#define CP_COMMIT() asm volatile("cp.async.commit_group;" ::: "memory")
#define CP_WAIT(n)  asm volatile("cp.async.wait_group %0;" :: "n"(n) : "memory")

__device__ __forceinline__ uint32_t pack_hl(float a, float b, uint32_t& lo) {
    __half ha = __float2half_rn(a), hb = __float2half_rn(b);
    __half la = __float2half_rn(a - __half2float(ha));
    __half lb = __float2half_rn(b - __half2float(hb));
    __half2 hh = __halves2half2(ha, hb);
    __half2 ll = __halves2half2(la, lb);
    lo = *(uint32_t*)&ll;
    return *(uint32_t*)&hh;
}

// ===========================================================================
// Split conversion for projections: fp32 [rows x 768] -> fp16 [rows x 2304]
// xmode=1: [hi | lo | hi]  (activations), xmode=0: [hi | hi | lo] (weights)
// ===========================================================================
__global__ void __launch_bounds__(256) conv_split_kernel(
    const float* __restrict__ in, __half* __restrict__ out,
    int rows, int xmode)
{
    const int t = blockIdx.x * 256 + threadIdx.x;
    const int total = rows * (DM / 4);
    if (t >= total) return;
    const int r  = t / (DM / 4);
    const int c4 = (t - r * (DM / 4)) * 4;
    const float4 v = *(const float4*)&in[(size_t)r * DM + c4];

    __half2 h01 = __float22half2_rn(make_float2(v.x, v.y));
    __half2 h23 = __float22half2_rn(make_float2(v.z, v.w));
    float2 hf01 = __half22float2(h01);
    float2 hf23 = __half22float2(h23);
    __half2 l01 = __float22half2_rn(make_float2(v.x - hf01.x, v.y - hf01.y));
    __half2 l23 = __float22half2_rn(make_float2(v.z - hf23.x, v.w - hf23.y));

    uint2 hi, lo;
    hi.x = *(uint32_t*)&h01; hi.y = *(uint32_t*)&h23;
    lo.x = *(uint32_t*)&l01; lo.y = *(uint32_t*)&l23;

    __half* orow = out + (size_t)r * KCAT;
    *(uint2*)&orow[c4]          = hi;
    *(uint2*)&orow[DM + c4]     = xmode ? lo : hi;
    *(uint2*)&orow[2 * DM + c4] = xmode ? hi : lo;
}

// ===========================================================================
// Attention input conversions.
// conv_qk: fp32 [8192][768] -> per-(b,h) fp16 [4096][192] split layout.
// ===========================================================================
__global__ void __launch_bounds__(256) conv_qk_kernel(
    const float* __restrict__ in, __half* __restrict__ out, int xmode)
{
    const int t = blockIdx.x * 256 + threadIdx.x;   // MROWS*12*16 threads
    const int c4  = (t & 15) * 4;
    const int h   = (t >> 4) % NHEAD;
    const int row = t / (16 * NHEAD);
    const float4 v = *(const float4*)&in[(size_t)row * DM + h * DKH + c4];

    __half2 h01 = __float22half2_rn(make_float2(v.x, v.y));
    __half2 h23 = __float22half2_rn(make_float2(v.z, v.w));
    float2 hf01 = __half22float2(h01);
    float2 hf23 = __half22float2(h23);
    __half2 l01 = __float22half2_rn(make_float2(v.x - hf01.x, v.y - hf01.y));
    __half2 l23 = __float22half2_rn(make_float2(v.z - hf23.x, v.w - hf23.y));

    uint2 hi, lo;
    hi.x = *(uint32_t*)&h01; hi.y = *(uint32_t*)&h23;
    lo.x = *(uint32_t*)&l01; lo.y = *(uint32_t*)&l23;

    const int b = row >> 12, s = row & 4095;
    __half* orow = out + ((size_t)(b * NHEAD + h) * SEQ + s) * DC;
    *(uint2*)&orow[c4]           = hi;
    *(uint2*)&orow[DKH + c4]     = xmode ? lo : hi;
    *(uint2*)&orow[2 * DKH + c4] = xmode ? hi : lo;
}

// conv_v: fp32 V -> per-(b,h) transposed fp16 Vt[128][SEQ] (hi rows 0-63, lo 64-127)
__global__ void __launch_bounds__(256) conv_v_kernel()
{
    __shared__ float vs[64][68];
    const int k0 = blockIdx.x * 64, h = blockIdx.y, b = blockIdx.z;
    const int tid = threadIdx.x;
#pragma unroll
    for (int t = 0; t < 4; t++) {
        const int u  = tid + t * 256;
        const int r  = u >> 4;
        const int c4 = (u & 15) * 4;
        *(float4*)&vs[r][c4] =
            *(const float4*)&g_V[(size_t)(b * SEQ + k0 + r) * DM + h * DKH + c4];
    }
    __syncthreads();
    const int d  = tid >> 2;
    const int kg = (tid & 3) * 16;
    uint4 hv[2], lv[2];
    __half* hb = (__half*)hv;
    __half* lb = (__half*)lv;
#pragma unroll
    for (int i = 0; i < 16; i++) {
        const float f = vs[kg + i][d];
        const __half hh = __float2half_rn(f);
        hb[i] = hh;
        lb[i] = __float2half_rn(f - __half2float(hh));
    }
    __half* dhi = g_Vt + ((size_t)(b * NHEAD + h) * 128 + d) * SEQ + k0 + kg;
    __half* dlo = dhi + (size_t)64 * SEQ;
    *(uint4*)dhi = hv[0]; *((uint4*)dhi + 1) = hv[1];
    *(uint4*)dlo = lv[0]; *((uint4*)dlo + 1) = lv[1];
}

// ===========================================================================
// Tensor-core GEMM (unchanged from R6, validated): C = Xcat . Wcat^T + bias
// ===========================================================================
#define BKC       64
#define SM_STR    72
#define TILE_B    (128 * SM_STR * 2)
#define GS_TOTAL  (4 * TILE_B)               // 73728 B
#define NCHUNK    (KCAT / BKC)               // 36

__global__ void __launch_bounds__(256)
tc_gemm_kernel(const __half* __restrict__ Xc,
               const __half* __restrict__ Wc,
               const float* __restrict__ bias,
               float* __restrict__ C)
{
    extern __shared__ char smem[];
    const uint32_t sbase = smem_u32(smem);
    const uint32_t aBuf[2] = { sbase,              sbase + TILE_B };
    const uint32_t bBuf[2] = { sbase + 2 * TILE_B, sbase + 3 * TILE_B };

    const int tid = threadIdx.x;
    const int wid = tid >> 5;
    const int L   = tid & 31;
    const int wm  = wid & 1;
    const int wn  = wid >> 1;
    const int bm0 = blockIdx.x * 128;
    const int bn0 = blockIdx.y * 128;

    const int aRow = (L & 7) + ((L >> 3) & 1) * 8;
    const int aK   = ((L >> 4) & 1) * 8;
    const int bRow = (L & 7) + ((L >> 4) & 1) * 8;
    const int bK   = ((L >> 3) & 1) * 8;
    const uint32_t aOff = ((wm * 64 + aRow) * SM_STR + aK) * 2;
    const uint32_t bOff = ((wn * 32 + bRow) * SM_STR + bK) * 2;

    float acc[4][4][4];
#pragma unroll
    for (int mt = 0; mt < 4; mt++)
#pragma unroll
        for (int nt = 0; nt < 4; nt++)
#pragma unroll
            for (int i = 0; i < 4; i++) acc[mt][nt][i] = 0.f;

    auto issue = [&](int c) {
        const int buf = c & 1;
#pragma unroll
        for (int t = 0; t < 4; t++) {
            const int u  = tid + t * 256;
            const int r  = u >> 3;
            const int c8 = (u & 7) * 8;
            cp16(aBuf[buf] + (r * SM_STR + c8) * 2,
                 &Xc[(size_t)(bm0 + r) * KCAT + c * BKC + c8]);
            cp16(bBuf[buf] + (r * SM_STR + c8) * 2,
                 &Wc[(size_t)(bn0 + r) * KCAT + c * BKC + c8]);
        }
        CP_COMMIT();
    };

    issue(0);
    for (int c = 0; c < NCHUNK; ++c) {
        const int buf = c & 1;
        if (c + 1 < NCHUNK) { issue(c + 1); CP_WAIT(1); }
        else                { CP_WAIT(0); }
        __syncthreads();
#pragma unroll
        for (int ks = 0; ks < 4; ++ks) {
            uint32_t af[4][4];
#pragma unroll
            for (int mt = 0; mt < 4; mt++)
                ldsm4(af[mt], aBuf[buf] + aOff + (mt * 16 * SM_STR + ks * 16) * 2);
            uint32_t bf[2][4];
#pragma unroll
            for (int np = 0; np < 2; np++)
                ldsm4(bf[np], bBuf[buf] + bOff + (np * 16 * SM_STR + ks * 16) * 2);
#pragma unroll
            for (int mt = 0; mt < 4; mt++)
#pragma unroll
                for (int nt = 0; nt < 4; nt++)
                    mma16816(acc[mt][nt], af[mt],
                             bf[nt >> 1][(nt & 1) * 2],
                             bf[nt >> 1][(nt & 1) * 2 + 1]);
        }
        __syncthreads();
    }

    const int qr = L >> 2;
    const int qc = (L & 3) * 2;
#pragma unroll
    for (int mt = 0; mt < 4; mt++) {
        const int row0 = bm0 + wm * 64 + mt * 16 + qr;
#pragma unroll
        for (int nt = 0; nt < 4; nt++) {
            const int col = bn0 + wn * 32 + nt * 8 + qc;
            const float2 bv = *(const float2*)&bias[col];
            const float* cc = acc[mt][nt];
            *(float2*)&C[(size_t)row0 * DM + col] =
                make_float2(cc[0] + bv.x, cc[1] + bv.y);
            *(float2*)&C[(size_t)(row0 + 8) * DM + col] =
                make_float2(cc[2] + bv.x, cc[3] + bv.y);
        }
    }
}

// ===========================================================================
// Tensor-core flash attention.
// CTA: 128 q-rows x one (b,h); 8 warps (warp = 16 q-rows); k-tiles of 64.
// Smem: Qs[128][200] | Ks[2][64][200] | Vts[2][128][72] | msk[2][64]
// ===========================================================================
#define QS_STR  200
#define VT_STR  72
#define AS_Q    0
#define AS_K    51200
#define AS_V    102400
#define AS_M    139264
#define AS_TOT  139776

__global__ void __launch_bounds__(256, 1)
attn_tc_kernel(const int* __restrict__ mask)
{
    extern __shared__ char sm[];
    const uint32_t sb = smem_u32(sm);
    const int tid = threadIdx.x;
    const int wid = tid >> 5;
    const int L   = tid & 31;
    const int qt  = gridDim.x - 1 - blockIdx.x;   // heavy tiles first
    const int h   = blockIdx.y;
    const int b   = blockIdx.z;
    const int q0  = qt * 128;
    const int nkt = 2 * (qt + 1);

    const __half* Qc = g_Qc + (size_t)(b * NHEAD + h) * SEQ * DC;
    const __half* Kc = g_Kc + (size_t)(b * NHEAD + h) * SEQ * DC;
    const __half* Vt = g_Vt + (size_t)(b * NHEAD + h) * 128 * SEQ;
    const int* mrow_g = mask + b * SEQ;

    // Prologue: Q tile + stage 0, then stage 1.
#pragma unroll
    for (int t = 0; t < 12; t++) {
        const int u = tid + t * 256;              // 3072 units
        const int r = u / 24, c = u % 24;
        cp16(sb + AS_Q + r * (QS_STR * 2) + c * 16,
             Qc + (size_t)(q0 + r) * DC + c * 8);
    }
    auto issueKV = [&](int i) {
        const uint32_t kb = sb + AS_K + (i & 1) * 25600;
        const uint32_t vb = sb + AS_V + (i & 1) * 18432;
#pragma unroll
        for (int t = 0; t < 6; t++) {
            const int u = tid + t * 256;          // 1536 units
            const int r = u / 24, c = u % 24;
            cp16(kb + r * (QS_STR * 2) + c * 16,
                 Kc + (size_t)(i * 64 + r) * DC + c * 8);
        }
#pragma unroll
        for (int t = 0; t < 4; t++) {
            const int u = tid + t * 256;          // 1024 units
            const int r = u >> 3, c = u & 7;
            cp16(vb + r * (VT_STR * 2) + c * 16,
                 Vt + (size_t)r * SEQ + i * 64 + c * 8);
        }
        if (tid < 16)
            cp16(sb + AS_M + (i & 1) * 256 + tid * 16, mrow_g + i * 64 + tid * 4);
    };
    issueKV(0); CP_COMMIT();
    if (nkt > 1) issueKV(1);
    CP_COMMIT();

    // Frag address components (identical mapping to tc_gemm, validated).
    const int aRow = (L & 7) + ((L >> 3) & 1) * 8;
    const int aK   = ((L >> 4) & 1) * 8;
    const int bRow = (L & 7) + ((L >> 4) & 1) * 8;
    const int bK   = ((L >> 3) & 1) * 8;
    const uint32_t aBase = sb + AS_Q + ((wid * 16 + aRow) * QS_STR + aK) * 2;
    const int lr  = L >> 2;
    const int lc2 = (L & 3) * 2;
    const int r0  = q0 + wid * 16 + lr;

    float sO[8][4];
#pragma unroll
    for (int nd = 0; nd < 8; nd++)
#pragma unroll
        for (int i = 0; i < 4; i++) sO[nd][i] = 0.f;
    float m[2] = { -INFINITY, -INFINITY };
    float l[2] = { 0.f, 0.f };

    for (int kt = 0; kt < nkt; ++kt) {
        const int buf = kt & 1;
        const int k0  = kt * 64;
        CP_WAIT(1);
        __syncthreads();

        const uint32_t kBase = sb + AS_K + buf * 25600 + (bRow * QS_STR + bK) * 2;
        const uint32_t vBase = sb + AS_V + buf * 18432 + (bRow * VT_STR + bK) * 2;
        const int* msk = (const int*)(sm + AS_M + buf * 256);

        // ---- S = Qcat . Kcat^T over d=192 ----
        float sS[8][4];
#pragma unroll
        for (int nt = 0; nt < 8; nt++)
#pragma unroll
            for (int i = 0; i < 4; i++) sS[nt][i] = 0.f;
#pragma unroll
        for (int ks = 0; ks < 12; ++ks) {
            uint32_t af[4];
            ldsm4(af, aBase + ks * 32);
            uint32_t bf[4][4];
#pragma unroll
            for (int np = 0; np < 4; np++)
                ldsm4(bf[np], kBase + (np * 16 * QS_STR + ks * 16) * 2);
#pragma unroll
            for (int nt = 0; nt < 8; nt++)
                mma16816(sS[nt], af,
                         bf[nt >> 1][(nt & 1) * 2],
                         bf[nt >> 1][(nt & 1) * 2 + 1]);
        }

        // ---- scale + masks ----
        const bool dg = (kt + 2 >= nkt);
#pragma unroll
        for (int nt = 0; nt < 8; nt++) {
            const int cr = nt * 8 + lc2;
            const int cg = k0 + cr;
            const int m0 = msk[cr], m1 = msk[cr + 1];
            float v0 = sS[nt][0] * 0.125f, v1 = sS[nt][1] * 0.125f;
            float v2 = sS[nt][2] * 0.125f, v3 = sS[nt][3] * 0.125f;
            if (m0 == 0) { v0 = NEGINF; v2 = NEGINF; }
            if (m1 == 0) { v1 = NEGINF; v3 = NEGINF; }
            if (dg) {
                if (cg > r0)         v0 = NEGINF;
                if (cg + 1 > r0)     v1 = NEGINF;
                if (cg > r0 + 8)     v2 = NEGINF;
                if (cg + 1 > r0 + 8) v3 = NEGINF;
            }
            sS[nt][0] = v0; sS[nt][1] = v1; sS[nt][2] = v2; sS[nt][3] = v3;
        }

        // ---- online softmax (rows owned by 4-lane groups) ----
#pragma unroll
        for (int i = 0; i < 2; i++) {
            float rm = -INFINITY;
#pragma unroll
            for (int nt = 0; nt < 8; nt++)
                rm = fmaxf(rm, fmaxf(sS[nt][i * 2], sS[nt][i * 2 + 1]));
            rm = fmaxf(rm, __shfl_xor_sync(0xffffffffu, rm, 1));
            rm = fmaxf(rm, __shfl_xor_sync(0xffffffffu, rm, 2));
            const float mn   = fmaxf(m[i], rm);
            const float corr = __expf(m[i] - mn);
            float rs = 0.f;
#pragma unroll
            for (int nt = 0; nt < 8; nt++) {
                sS[nt][i * 2]     = __expf(sS[nt][i * 2] - mn);
                sS[nt][i * 2 + 1] = __expf(sS[nt][i * 2 + 1] - mn);
                rs += sS[nt][i * 2] + sS[nt][i * 2 + 1];
            }
            rs += __shfl_xor_sync(0xffffffffu, rs, 1);
            rs += __shfl_xor_sync(0xffffffffu, rs, 2);
            l[i] = l[i] * corr + rs;
            m[i] = mn;
#pragma unroll
            for (int nd = 0; nd < 8; nd++) {
                sO[nd][i * 2]     *= corr;
                sO[nd][i * 2 + 1] *= corr;
            }
        }

        // ---- O += (Phi+Plo).Vhi + Phi.Vlo  (acc frags reused as PV A-frags) ----
#pragma unroll
        for (int t = 0; t < 4; t++) {
            uint32_t ah[4], al[4];
            ah[0] = pack_hl(sS[2 * t][0],     sS[2 * t][1],     al[0]);
            ah[1] = pack_hl(sS[2 * t][2],     sS[2 * t][3],     al[1]);
            ah[2] = pack_hl(sS[2 * t + 1][0], sS[2 * t + 1][1], al[2]);
            ah[3] = pack_hl(sS[2 * t + 1][2], sS[2 * t + 1][3], al[3]);
            uint32_t bv[4][4];
#pragma unroll
            for (int np = 0; np < 4; np++)      // V-hi rows 0-63
                ldsm4(bv[np], vBase + (np * 16 * VT_STR + t * 16) * 2);
#pragma unroll
            for (int nd = 0; nd < 8; nd++) {
                mma16816(sO[nd], ah, bv[nd >> 1][(nd & 1) * 2],
                         bv[nd >> 1][(nd & 1) * 2 + 1]);
                mma16816(sO[nd], al, bv[nd >> 1][(nd & 1) * 2],
                         bv[nd >> 1][(nd & 1) * 2 + 1]);
            }
#pragma unroll
            for (int np = 0; np < 4; np++)      // V-lo rows 64-127
                ldsm4(bv[np], vBase + ((64 + np * 16) * VT_STR + t * 16) * 2);
#pragma unroll
            for (int nd = 0; nd < 8; nd++)
                mma16816(sO[nd], ah, bv[nd >> 1][(nd & 1) * 2],
                         bv[nd >> 1][(nd & 1) * 2 + 1]);
        }

        __syncthreads();
        if (kt + 2 < nkt) issueKV(kt + 2);
        CP_COMMIT();
    }

    // ---- epilogue: normalize, write g_A[row][h*64 + d] ----
#pragma unroll
    for (int i = 0; i < 2; i++) {
        const float inv = 1.f / l[i];
        float* dst = g_A + ((size_t)b * SEQ + r0 + i * 8) * DM + h * DKH;
#pragma unroll
        for (int nd = 0; nd < 8; nd++)
            *(float2*)&dst[nd * 8 + lc2] =
                make_float2(sO[nd][i * 2] * inv, sO[nd][i * 2 + 1] * inv);
    }
}

// ===========================================================================
// Launch
// ===========================================================================
extern "C" void kernel_launch(void* const* d_in, const int* in_sizes, int n_in,
                              void* d_out, int out_size)
{
    const float* query = (const float*)d_in[0];
    const float* key   = (const float*)d_in[1];
    const float* value = (const float*)d_in[2];
    const int*   mask  = (const int*)  d_in[3];
    const float* Wq    = (const float*)d_in[4];
    const float* bq    = (const float*)d_in[5];
    const float* Wk    = (const float*)d_in[6];
    const float* bk    = (const float*)d_in[7];
    const float* Wv    = (const float*)d_in[8];
    const float* bv    = (const float*)d_in[9];
    const float* Wo    = (const float*)d_in[10];
    const float* bo    = (const float*)d_in[11];
    float* out = (float*)d_out;

    float *Qb, *Kb, *Vb, *Ab;
    __half *Xcat, *Wcat, *Qcp, *Kcp;
    cudaGetSymbolAddress((void**)&Qb, g_Q);
    cudaGetSymbolAddress((void**)&Kb, g_K);
    cudaGetSymbolAddress((void**)&Vb, g_V);
    cudaGetSymbolAddress((void**)&Ab, g_A);
    cudaGetSymbolAddress((void**)&Xcat, g_Xcat);
    cudaGetSymbolAddress((void**)&Wcat, g_Wcat);
    cudaGetSymbolAddress((void**)&Qcp, g_Qc);
    cudaGetSymbolAddress((void**)&Kcp, g_Kc);

    cudaFuncSetAttribute(tc_gemm_kernel,
                         cudaFuncAttributeMaxDynamicSharedMemorySize, GS_TOTAL);
    cudaFuncSetAttribute(attn_tc_kernel,
                         cudaFuncAttributeMaxDynamicSharedMemorySize, AS_TOT);

    const int convX_blocks = (MROWS * (DM / 4) + 255) / 256;  // 6144
    const int convW_blocks = (DM * (DM / 4) + 255) / 256;     // 576
    const int convA_blocks = MROWS * NHEAD * 16 / 256;        // 6144
    const dim3 ggrid(MROWS / 128, DM / 128);                  // (64, 6)

    // Projections
    conv_split_kernel<<<convX_blocks, 256>>>(query, Xcat, MROWS, 1);
    conv_split_kernel<<<convW_blocks, 256>>>(Wq, Wcat, DM, 0);
    tc_gemm_kernel<<<ggrid, 256, GS_TOTAL>>>(Xcat, Wcat, bq, Qb);
    conv_split_kernel<<<convX_blocks, 256>>>(key, Xcat, MROWS, 1);
    conv_split_kernel<<<convW_blocks, 256>>>(Wk, Wcat, DM, 0);
    tc_gemm_kernel<<<ggrid, 256, GS_TOTAL>>>(Xcat, Wcat, bk, Kb);
    conv_split_kernel<<<convX_blocks, 256>>>(value, Xcat, MROWS, 1);
    conv_split_kernel<<<convW_blocks, 256>>>(Wv, Wcat, DM, 0);
    tc_gemm_kernel<<<ggrid, 256, GS_TOTAL>>>(Xcat, Wcat, bv, Vb);

    // Attention input conversions
    conv_qk_kernel<<<convA_blocks, 256>>>(Qb, Qcp, 1);
    conv_qk_kernel<<<convA_blocks, 256>>>(Kb, Kcp, 0);
    conv_v_kernel<<<dim3(SEQ / 64, NHEAD, BATCH), 256>>>();

    // Tensor-core flash attention
    attn_tc_kernel<<<dim3(SEQ / 128, NHEAD, BATCH), 256, AS_TOT>>>(mask);

    // Output projection
    conv_split_kernel<<<convX_blocks, 256>>>(Ab, Xcat, MROWS, 1);
    conv_split_kernel<<<convW_blocks, 256>>>(Wo, Wcat, DM, 0);
    tc_gemm_kernel<<<ggrid, 256, GS_TOTAL>>>(Xcat, Wcat, bo, out);
}

// round 12
// speedup vs baseline: 2.9583x; 1.2532x over previous
#include <cuda_runtime.h>
#include <cuda_fp16.h>
#include <math.h>
#include <stdint.h>

// Problem constants (fixed by the reference).
#define BATCH   2
#define SEQ     4096
#define DM      768
#define NHEAD   12
#define DKH     64
#define MROWS   (BATCH * SEQ)   // 8192
#define KCAT    (3 * DM)        // 2304: [hi | lo | hi] x [hi | hi | lo]
#define DC2     128             // 2-seg concat head dim for QK
#define NEGINF  (-1e9f)

// Scratch (allocation-free: __device__ globals).
__device__ float g_V[MROWS * DM];
__device__ float g_A[MROWS * DM];
__device__ __half g_Xcat[(size_t)MROWS * KCAT];             // 37.7 MB
__device__ __half g_Wcat[(size_t)DM * KCAT];                // 3.5 MB
__device__ __half g_Qc[(size_t)BATCH * NHEAD * SEQ * DC2];  // 25.2 MB [hi|lo]
__device__ __half g_Kc[(size_t)BATCH * NHEAD * SEQ * DC2];  // 25.2 MB [hi|hi]
__device__ __half g_Vt[(size_t)BATCH * NHEAD * 64 * SEQ];   // 12.6 MB (hi only)

// ===========================================================================
// Warp-MMA helpers (sm_80+ path, legal on plain sm_103)
// ===========================================================================
__device__ __forceinline__ uint32_t smem_u32(const void* p) {
    uint32_t a;
    asm("{ .reg .u64 t; cvta.to.shared.u64 t, %1; cvt.u32.u64 %0, t; }"
        : "=r"(a) : "l"(p));
    return a;
}
__device__ __forceinline__ void ldsm4(uint32_t* r, uint32_t addr) {
    asm volatile("ldmatrix.sync.aligned.m8n8.x4.shared.b16 {%0,%1,%2,%3}, [%4];"
                 : "=r"(r[0]), "=r"(r[1]), "=r"(r[2]), "=r"(r[3]) : "r"(addr));
}
__device__ __forceinline__ void mma16816(float* c, const uint32_t* a,
                                         uint32_t b0, uint32_t b1) {
    asm volatile(
        "mma.sync.aligned.m16n8k16.row.col.f32.f16.f16.f32 "
        "{%0,%1,%2,%3}, {%4,%5,%6,%7}, {%8,%9}, {%0,%1,%2,%3};"
        : "+f"(c[0]), "+f"(c[1]), "+f"(c[2]), "+f"(c[3])
        : "r"(a[0]), "r"(a[1]), "r"(a[2]), "r"(a[3]), "r"(b0), "r"(b1));
}
__device__ __forceinline__ void cp16(uint32_t dst, const void* src) {
    asm volatile("cp.async.cg.shared.global [%0], [%1], 16;"
                 :: "r"(dst), "l"(src));
}
#define CP_COMMIT() asm volatile("cp.async.commit_group;" ::: "memory")
#define CP_WAIT(n)  asm volatile("cp.async.wait_group %0;" :: "n"(n) : "memory")

__device__ __forceinline__ uint32_t pack_hl(float a, float b, uint32_t& lo) {
    __half ha = __float2half_rn(a), hb = __float2half_rn(b);
    __half la = __float2half_rn(a - __half2float(ha));
    __half lb = __float2half_rn(b - __half2float(hb));
    __half2 hh = __halves2half2(ha, hb);
    __half2 ll = __halves2half2(la, lb);
    lo = *(uint32_t*)&ll;
    return *(uint32_t*)&hh;
}

// ===========================================================================
// Split conversion for projections: fp32 [rows x 768] -> fp16 [rows x 2304]
// xmode=1: [hi | lo | hi]  (activations), xmode=0: [hi | hi | lo] (weights)
// ===========================================================================
__global__ void __launch_bounds__(256) conv_split_kernel(
    const float* __restrict__ in, __half* __restrict__ out,
    int rows, int xmode)
{
    const int t = blockIdx.x * 256 + threadIdx.x;
    const int total = rows * (DM / 4);
    if (t >= total) return;
    const int r  = t / (DM / 4);
    const int c4 = (t - r * (DM / 4)) * 4;
    const float4 v = *(const float4*)&in[(size_t)r * DM + c4];

    __half2 h01 = __float22half2_rn(make_float2(v.x, v.y));
    __half2 h23 = __float22half2_rn(make_float2(v.z, v.w));
    float2 hf01 = __half22float2(h01);
    float2 hf23 = __half22float2(h23);
    __half2 l01 = __float22half2_rn(make_float2(v.x - hf01.x, v.y - hf01.y));
    __half2 l23 = __float22half2_rn(make_float2(v.z - hf23.x, v.w - hf23.y));

    uint2 hi, lo;
    hi.x = *(uint32_t*)&h01; hi.y = *(uint32_t*)&h23;
    lo.x = *(uint32_t*)&l01; lo.y = *(uint32_t*)&l23;

    __half* orow = out + (size_t)r * KCAT;
    *(uint2*)&orow[c4]          = hi;
    *(uint2*)&orow[DM + c4]     = xmode ? lo : hi;
    *(uint2*)&orow[2 * DM + c4] = xmode ? hi : lo;
}

// conv_v: fp32 V -> per-(b,h) transposed fp16 Vt[64][SEQ] (hi only)
__global__ void __launch_bounds__(256) conv_v_kernel()
{
    __shared__ float vs[64][68];
    const int k0 = blockIdx.x * 64, h = blockIdx.y, b = blockIdx.z;
    const int tid = threadIdx.x;
#pragma unroll
    for (int t = 0; t < 4; t++) {
        const int u  = tid + t * 256;
        const int r  = u >> 4;
        const int c4 = (u & 15) * 4;
        *(float4*)&vs[r][c4] =
            *(const float4*)&g_V[(size_t)(b * SEQ + k0 + r) * DM + h * DKH + c4];
    }
    __syncthreads();
    const int d  = tid >> 2;
    const int kg = (tid & 3) * 16;
    uint4 hv[2];
    __half* hb = (__half*)hv;
#pragma unroll
    for (int i = 0; i < 16; i++)
        hb[i] = __float2half_rn(vs[kg + i][d]);
    __half* dhi = g_Vt + ((size_t)(b * NHEAD + h) * 64 + d) * SEQ + k0 + kg;
    *(uint4*)dhi = hv[0]; *((uint4*)dhi + 1) = hv[1];
}

// ===========================================================================
// Tensor-core GEMM: C = Xcat . Wcat^T + bias
// Epilogue modes: 0 = fp32 to C; 1 = per-head split fp16 [hi|lo] to Cc (Q);
//                 2 = per-head fp16 [hi|hi] to Cc (K).
// ===========================================================================
#define BKC       64
#define SM_STR    72
#define TILE_B    (128 * SM_STR * 2)
#define GS_TOTAL  (4 * TILE_B)               // 73728 B
#define NCHUNK    (KCAT / BKC)               // 36

__global__ void __launch_bounds__(256)
tc_gemm_kernel(const __half* __restrict__ Xc,
               const __half* __restrict__ Wc,
               const float* __restrict__ bias,
               float* __restrict__ C,
               __half* __restrict__ Cc,
               int mode)
{
    extern __shared__ char smem[];
    const uint32_t sbase = smem_u32(smem);
    const uint32_t aBuf[2] = { sbase,              sbase + TILE_B };
    const uint32_t bBuf[2] = { sbase + 2 * TILE_B, sbase + 3 * TILE_B };

    const int tid = threadIdx.x;
    const int wid = tid >> 5;
    const int L   = tid & 31;
    const int wm  = wid & 1;
    const int wn  = wid >> 1;
    const int bm0 = blockIdx.x * 128;
    const int bn0 = blockIdx.y * 128;

    const int aRow = (L & 7) + ((L >> 3) & 1) * 8;
    const int aK   = ((L >> 4) & 1) * 8;
    const int bRow = (L & 7) + ((L >> 4) & 1) * 8;
    const int bK   = ((L >> 3) & 1) * 8;
    const uint32_t aOff = ((wm * 64 + aRow) * SM_STR + aK) * 2;
    const uint32_t bOff = ((wn * 32 + bRow) * SM_STR + bK) * 2;

    float acc[4][4][4];
#pragma unroll
    for (int mt = 0; mt < 4; mt++)
#pragma unroll
        for (int nt = 0; nt < 4; nt++)
#pragma unroll
            for (int i = 0; i < 4; i++) acc[mt][nt][i] = 0.f;

    auto issue = [&](int c) {
        const int buf = c & 1;
#pragma unroll
        for (int t = 0; t < 4; t++) {
            const int u  = tid + t * 256;
            const int r  = u >> 3;
            const int c8 = (u & 7) * 8;
            cp16(aBuf[buf] + (r * SM_STR + c8) * 2,
                 &Xc[(size_t)(bm0 + r) * KCAT + c * BKC + c8]);
            cp16(bBuf[buf] + (r * SM_STR + c8) * 2,
                 &Wc[(size_t)(bn0 + r) * KCAT + c * BKC + c8]);
        }
        CP_COMMIT();
    };

    issue(0);
    for (int c = 0; c < NCHUNK; ++c) {
        const int buf = c & 1;
        if (c + 1 < NCHUNK) { issue(c + 1); CP_WAIT(1); }
        else                { CP_WAIT(0); }
        __syncthreads();
#pragma unroll
        for (int ks = 0; ks < 4; ++ks) {
            uint32_t af[4][4];
#pragma unroll
            for (int mt = 0; mt < 4; mt++)
                ldsm4(af[mt], aBuf[buf] + aOff + (mt * 16 * SM_STR + ks * 16) * 2);
            uint32_t bf[2][4];
#pragma unroll
            for (int np = 0; np < 2; np++)
                ldsm4(bf[np], bBuf[buf] + bOff + (np * 16 * SM_STR + ks * 16) * 2);
#pragma unroll
            for (int mt = 0; mt < 4; mt++)
#pragma unroll
                for (int nt = 0; nt < 4; nt++)
                    mma16816(acc[mt][nt], af[mt],
                             bf[nt >> 1][(nt & 1) * 2],
                             bf[nt >> 1][(nt & 1) * 2 + 1]);
        }
        __syncthreads();
    }

    const int qr = L >> 2;
    const int qc = (L & 3) * 2;
#pragma unroll
    for (int mt = 0; mt < 4; mt++) {
        const int row0 = bm0 + wm * 64 + mt * 16 + qr;
#pragma unroll
        for (int nt = 0; nt < 4; nt++) {
            const int col = bn0 + wn * 32 + nt * 8 + qc;
            const float2 bv = *(const float2*)&bias[col];
            const float* cc = acc[mt][nt];
            const float a0 = cc[0] + bv.x, a1 = cc[1] + bv.y;
            const float a2 = cc[2] + bv.x, a3 = cc[3] + bv.y;
            if (mode == 0) {
                *(float2*)&C[(size_t)row0 * DM + col]       = make_float2(a0, a1);
                *(float2*)&C[(size_t)(row0 + 8) * DM + col] = make_float2(a2, a3);
            } else {
                const int b = row0 >> 12, s = row0 & 4095;
                const int h = col >> 6, d = col & 63;
                __half* o0 = Cc + ((size_t)(b * NHEAD + h) * SEQ + s) * DC2;
                __half* o1 = o0 + 8 * DC2;
                uint32_t lo0, lo1;
                const uint32_t hi0 = pack_hl(a0, a1, lo0);
                const uint32_t hi1 = pack_hl(a2, a3, lo1);
                *(uint32_t*)&o0[d]      = hi0;
                *(uint32_t*)&o0[64 + d] = (mode == 1) ? lo0 : hi0;
                *(uint32_t*)&o1[d]      = hi1;
                *(uint32_t*)&o1[64 + d] = (mode == 1) ? lo1 : hi1;
            }
        }
    }
}

// ===========================================================================
// Tensor-core flash attention (2-seg QK, 2-pass PV).
// CTA: 128 q-rows x one (b,h); 8 warps; k-tiles of 64; 2 CTAs/SM.
// Smem: Qs[128][136] | Ks[2][64][136] | Vts[2][64][72] | msk[2][64]
// ===========================================================================
#define QS_STR  136
#define VT_STR  72
#define KBUF    17408
#define VBUF    9216
#define AS_Q    0
#define AS_K    34816
#define AS_V    69632
#define AS_M    88064
#define AS_TOT  88576

__global__ void __launch_bounds__(256, 2)
attn_tc_kernel(const int* __restrict__ mask)
{
    extern __shared__ char sm[];
    const uint32_t sb = smem_u32(sm);
    const int tid = threadIdx.x;
    const int wid = tid >> 5;
    const int L   = tid & 31;
    const int qt  = gridDim.x - 1 - blockIdx.x;   // heavy tiles first
    const int h   = blockIdx.y;
    const int b   = blockIdx.z;
    const int q0  = qt * 128;
    const int nkt = 2 * (qt + 1);

    const __half* Qc = g_Qc + (size_t)(b * NHEAD + h) * SEQ * DC2;
    const __half* Kc = g_Kc + (size_t)(b * NHEAD + h) * SEQ * DC2;
    const __half* Vt = g_Vt + (size_t)(b * NHEAD + h) * 64 * SEQ;
    const int* mrow_g = mask + b * SEQ;

    // Prologue: Q tile (2048 x 16B) + stages 0,1.
#pragma unroll
    for (int t = 0; t < 8; t++) {
        const int u = tid + t * 256;
        const int r = u >> 4, c = u & 15;
        cp16(sb + AS_Q + (r * QS_STR + c * 8) * 2,
             Qc + (size_t)(q0 + r) * DC2 + c * 8);
    }
    auto issueKV = [&](int i) {
        const uint32_t kb = sb + AS_K + (i & 1) * KBUF;
        const uint32_t vb = sb + AS_V + (i & 1) * VBUF;
#pragma unroll
        for (int t = 0; t < 4; t++) {
            const int u = tid + t * 256;          // 1024 units
            const int r = u >> 4, c = u & 15;
            cp16(kb + (r * QS_STR + c * 8) * 2,
                 Kc + (size_t)(i * 64 + r) * DC2 + c * 8);
        }
#pragma unroll
        for (int t = 0; t < 2; t++) {
            const int u = tid + t * 256;          // 512 units
            const int r = u >> 3, c = u & 7;
            cp16(vb + (r * VT_STR + c * 8) * 2,
                 Vt + (size_t)r * SEQ + i * 64 + c * 8);
        }
        if (tid < 16)
            cp16(sb + AS_M + (i & 1) * 256 + tid * 16, mrow_g + i * 64 + tid * 4);
    };
    issueKV(0); CP_COMMIT();
    issueKV(1); CP_COMMIT();

    // Frag address components (same mapping as tc_gemm, validated).
    const int aRow = (L & 7) + ((L >> 3) & 1) * 8;
    const int aK   = ((L >> 4) & 1) * 8;
    const int bRow = (L & 7) + ((L >> 4) & 1) * 8;
    const int bK   = ((L >> 3) & 1) * 8;
    const uint32_t aBase = sb + AS_Q + ((wid * 16 + aRow) * QS_STR + aK) * 2;
    const int lr  = L >> 2;
    const int lc2 = (L & 3) * 2;
    const int r0  = q0 + wid * 16 + lr;

    float sO[8][4];
#pragma unroll
    for (int nd = 0; nd < 8; nd++)
#pragma unroll
        for (int i = 0; i < 4; i++) sO[nd][i] = 0.f;
    float m[2] = { -INFINITY, -INFINITY };
    float l[2] = { 0.f, 0.f };

    for (int kt = 0; kt < nkt; ++kt) {
        const int buf = kt & 1;
        const int k0  = kt * 64;
        CP_WAIT(1);
        __syncthreads();

        const uint32_t kBase = sb + AS_K + buf * KBUF + (bRow * QS_STR + bK) * 2;
        const uint32_t vBase = sb + AS_V + buf * VBUF + (bRow * VT_STR + bK) * 2;
        const int* msk = (const int*)(sm + AS_M + buf * 256);

        // ---- S = [Qhi|Qlo] . [Khi|Khi]^T over d=128 ----
        float sS[8][4];
#pragma unroll
        for (int nt = 0; nt < 8; nt++)
#pragma unroll
            for (int i = 0; i < 4; i++) sS[nt][i] = 0.f;
#pragma unroll
        for (int ks = 0; ks < 8; ++ks) {
            uint32_t af[4];
            ldsm4(af, aBase + ks * 32);
            uint32_t bf[4][4];
#pragma unroll
            for (int np = 0; np < 4; np++)
                ldsm4(bf[np], kBase + (np * 16 * QS_STR + ks * 16) * 2);
#pragma unroll
            for (int nt = 0; nt < 8; nt++)
                mma16816(sS[nt], af,
                         bf[nt >> 1][(nt & 1) * 2],
                         bf[nt >> 1][(nt & 1) * 2 + 1]);
        }

        // ---- scale + masks ----
        const bool dg = (kt + 2 >= nkt);
#pragma unroll
        for (int nt = 0; nt < 8; nt++) {
            const int cr = nt * 8 + lc2;
            const int cg = k0 + cr;
            const int m0 = msk[cr], m1 = msk[cr + 1];
            float v0 = sS[nt][0] * 0.125f, v1 = sS[nt][1] * 0.125f;
            float v2 = sS[nt][2] * 0.125f, v3 = sS[nt][3] * 0.125f;
            if (m0 == 0) { v0 = NEGINF; v2 = NEGINF; }
            if (m1 == 0) { v1 = NEGINF; v3 = NEGINF; }
            if (dg) {
                if (cg > r0)         v0 = NEGINF;
                if (cg + 1 > r0)     v1 = NEGINF;
                if (cg > r0 + 8)     v2 = NEGINF;
                if (cg + 1 > r0 + 8) v3 = NEGINF;
            }
            sS[nt][0] = v0; sS[nt][1] = v1; sS[nt][2] = v2; sS[nt][3] = v3;
        }

        // ---- online softmax (rows owned by 4-lane groups) ----
#pragma unroll
        for (int i = 0; i < 2; i++) {
            float rm = -INFINITY;
#pragma unroll
            for (int nt = 0; nt < 8; nt++)
                rm = fmaxf(rm, fmaxf(sS[nt][i * 2], sS[nt][i * 2 + 1]));
            rm = fmaxf(rm, __shfl_xor_sync(0xffffffffu, rm, 1));
            rm = fmaxf(rm, __shfl_xor_sync(0xffffffffu, rm, 2));
            const float mn   = fmaxf(m[i], rm);
            const float corr = __expf(m[i] - mn);
            float rs = 0.f;
#pragma unroll
            for (int nt = 0; nt < 8; nt++) {
                sS[nt][i * 2]     = __expf(sS[nt][i * 2] - mn);
                sS[nt][i * 2 + 1] = __expf(sS[nt][i * 2 + 1] - mn);
                rs += sS[nt][i * 2] + sS[nt][i * 2 + 1];
            }
            rs += __shfl_xor_sync(0xffffffffu, rs, 1);
            rs += __shfl_xor_sync(0xffffffffu, rs, 2);
            l[i] = l[i] * corr + rs;
            m[i] = mn;
#pragma unroll
            for (int nd = 0; nd < 8; nd++) {
                sO[nd][i * 2]     *= corr;
                sO[nd][i * 2 + 1] *= corr;
            }
        }

        // ---- O += (Phi+Plo).Vhi  (acc frags reused as PV A-frags) ----
#pragma unroll
        for (int t = 0; t < 4; t++) {
            uint32_t ah[4], al[4];
            ah[0] = pack_hl(sS[2 * t][0],     sS[2 * t][1],     al[0]);
            ah[1] = pack_hl(sS[2 * t][2],     sS[2 * t][3],     al[1]);
            ah[2] = pack_hl(sS[2 * t + 1][0], sS[2 * t + 1][1], al[2]);
            ah[3] = pack_hl(sS[2 * t + 1][2], sS[2 * t + 1][3], al[3]);
            uint32_t bv[4][4];
#pragma unroll
            for (int np = 0; np < 4; np++)
                ldsm4(bv[np], vBase + (np * 16 * VT_STR + t * 16) * 2);
#pragma unroll
            for (int nd = 0; nd < 8; nd++) {
                mma16816(sO[nd], ah, bv[nd >> 1][(nd & 1) * 2],
                         bv[nd >> 1][(nd & 1) * 2 + 1]);
                mma16816(sO[nd], al, bv[nd >> 1][(nd & 1) * 2],
                         bv[nd >> 1][(nd & 1) * 2 + 1]);
            }
        }

        __syncthreads();
        if (kt + 2 < nkt) issueKV(kt + 2);
        CP_COMMIT();
    }

    // ---- epilogue: normalize, write g_A[row][h*64 + d] ----
#pragma unroll
    for (int i = 0; i < 2; i++) {
        const float inv = 1.f / l[i];
        float* dst = g_A + ((size_t)b * SEQ + r0 + i * 8) * DM + h * DKH;
#pragma unroll
        for (int nd = 0; nd < 8; nd++)
            *(float2*)&dst[nd * 8 + lc2] =
                make_float2(sO[nd][i * 2] * inv, sO[nd][i * 2 + 1] * inv);
    }
}

// ===========================================================================
// Launch
// ===========================================================================
extern "C" void kernel_launch(void* const* d_in, const int* in_sizes, int n_in,
                              void* d_out, int out_size)
{
    const float* query = (const float*)d_in[0];
    const float* key   = (const float*)d_in[1];
    const float* value = (const float*)d_in[2];
    const int*   mask  = (const int*)  d_in[3];
    const float* Wq    = (const float*)d_in[4];
    const float* bq    = (const float*)d_in[5];
    const float* Wk    = (const float*)d_in[6];
    const float* bk    = (const float*)d_in[7];
    const float* Wv    = (const float*)d_in[8];
    const float* bv    = (const float*)d_in[9];
    const float* Wo    = (const float*)d_in[10];
    const float* bo    = (const float*)d_in[11];
    float* out = (float*)d_out;

    float *Vb, *Ab;
    __half *Xcat, *Wcat, *Qcp, *Kcp;
    cudaGetSymbolAddress((void**)&Vb, g_V);
    cudaGetSymbolAddress((void**)&Ab, g_A);
    cudaGetSymbolAddress((void**)&Xcat, g_Xcat);
    cudaGetSymbolAddress((void**)&Wcat, g_Wcat);
    cudaGetSymbolAddress((void**)&Qcp, g_Qc);
    cudaGetSymbolAddress((void**)&Kcp, g_Kc);

    cudaFuncSetAttribute(tc_gemm_kernel,
                         cudaFuncAttributeMaxDynamicSharedMemorySize, GS_TOTAL);
    cudaFuncSetAttribute(attn_tc_kernel,
                         cudaFuncAttributeMaxDynamicSharedMemorySize, AS_TOT);

    const int convX_blocks = (MROWS * (DM / 4) + 255) / 256;  // 6144
    const int convW_blocks = (DM * (DM / 4) + 255) / 256;     // 576
    const dim3 ggrid(MROWS / 128, DM / 128);                  // (64, 6)

    // Q projection -> g_Qc directly (split [hi|lo])
    conv_split_kernel<<<convX_blocks, 256>>>(query, Xcat, MROWS, 1);
    conv_split_kernel<<<convW_blocks, 256>>>(Wq, Wcat, DM, 0);
    tc_gemm_kernel<<<ggrid, 256, GS_TOTAL>>>(Xcat, Wcat, bq, nullptr, Qcp, 1);
    // K projection -> g_Kc directly ([hi|hi])
    conv_split_kernel<<<convX_blocks, 256>>>(key, Xcat, MROWS, 1);
    conv_split_kernel<<<convW_blocks, 256>>>(Wk, Wcat, DM, 0);
    tc_gemm_kernel<<<ggrid, 256, GS_TOTAL>>>(Xcat, Wcat, bk, nullptr, Kcp, 2);
    // V projection -> fp32 g_V, then transpose/convert (hi only)
    conv_split_kernel<<<convX_blocks, 256>>>(value, Xcat, MROWS, 1);
    conv_split_kernel<<<convW_blocks, 256>>>(Wv, Wcat, DM, 0);
    tc_gemm_kernel<<<ggrid, 256, GS_TOTAL>>>(Xcat, Wcat, bv, Vb, nullptr, 0);
    conv_v_kernel<<<dim3(SEQ / 64, NHEAD, BATCH), 256>>>();

    // Tensor-core flash attention
    attn_tc_kernel<<<dim3(SEQ / 128, NHEAD, BATCH), 256, AS_TOT>>>(mask);

    // Output projection
    conv_split_kernel<<<convX_blocks, 256>>>(Ab, Xcat, MROWS, 1);
    conv_split_kernel<<<convW_blocks, 256>>>(Wo, Wcat, DM, 0);
    tc_gemm_kernel<<<ggrid, 256, GS_TOTAL>>>(Xcat, Wcat, bo, out, nullptr, 0);
}

// round 14
// speedup vs baseline: 3.5191x; 1.1896x over previous
#include <cuda_runtime.h>
#include <cuda_fp16.h>
#include <math.h>
#include <stdint.h>

// Problem constants (fixed by the reference).
#define BATCH   2
#define SEQ     4096
#define DM      768
#define NHEAD   12
#define DKH     64
#define MROWS   (BATCH * SEQ)   // 8192
#define KCAT    (2 * DM)        // 1536: X=[hi|lo], W=[hi|hi]  ->  X . fp16(W)^T
#define DC2     128             // 2-seg concat head dim for QK
#define NEGINF  (-1e9f)

// Scratch (allocation-free: __device__ globals).
__device__ float g_V[MROWS * DM];
__device__ float g_A[MROWS * DM];
__device__ __half g_Xcat[(size_t)MROWS * KCAT];             // 25.2 MB
__device__ __half g_Wcat[(size_t)DM * KCAT];                // 2.25 MB
__device__ __half g_Qc[(size_t)BATCH * NHEAD * SEQ * DC2];  // 25.2 MB [hi|lo]
__device__ __half g_Kc[(size_t)BATCH * NHEAD * SEQ * DC2];  // 25.2 MB [hi|hi]
__device__ __half g_Vt[(size_t)BATCH * NHEAD * 64 * SEQ];   // 12.6 MB (hi only)

// ===========================================================================
// Warp-MMA helpers (sm_80+ path, legal on plain sm_103)
// ===========================================================================
__device__ __forceinline__ uint32_t smem_u32(const void* p) {
    uint32_t a;
    asm("{ .reg .u64 t; cvta.to.shared.u64 t, %1; cvt.u32.u64 %0, t; }"
        : "=r"(a) : "l"(p));
    return a;
}
__device__ __forceinline__ void ldsm4(uint32_t* r, uint32_t addr) {
    asm volatile("ldmatrix.sync.aligned.m8n8.x4.shared.b16 {%0,%1,%2,%3}, [%4];"
                 : "=r"(r[0]), "=r"(r[1]), "=r"(r[2]), "=r"(r[3]) : "r"(addr));
}
__device__ __forceinline__ void mma16816(float* c, const uint32_t* a,
                                         uint32_t b0, uint32_t b1) {
    asm volatile(
        "mma.sync.aligned.m16n8k16.row.col.f32.f16.f16.f32 "
        "{%0,%1,%2,%3}, {%4,%5,%6,%7}, {%8,%9}, {%0,%1,%2,%3};"
        : "+f"(c[0]), "+f"(c[1]), "+f"(c[2]), "+f"(c[3])
        : "r"(a[0]), "r"(a[1]), "r"(a[2]), "r"(a[3]), "r"(b0), "r"(b1));
}
__device__ __forceinline__ void cp16(uint32_t dst, const void* src) {
    asm volatile("cp.async.cg.shared.global [%0], [%1], 16;"
                 :: "r"(dst), "l"(src));
}
#define CP_COMMIT() asm volatile("cp.async.commit_group;" ::: "memory")
#define CP_WAIT(n)  asm volatile("cp.async.wait_group %0;" :: "n"(n) : "memory")

__device__ __forceinline__ uint32_t pack_hl(float a, float b, uint32_t& lo) {
    __half ha = __float2half_rn(a), hb = __float2half_rn(b);
    __half la = __float2half_rn(a - __half2float(ha));
    __half lb = __float2half_rn(b - __half2float(hb));
    __half2 hh = __halves2half2(ha, hb);
    __half2 ll = __halves2half2(la, lb);
    lo = *(uint32_t*)&ll;
    return *(uint32_t*)&hh;
}

// ===========================================================================
// Split conversion for projections: fp32 [rows x 768] -> fp16 [rows x 1536]
// xmode=1: [hi | lo]  (activations: exact to 22 bits)
// xmode=0: [hi | hi]  (weights: fp16-rounded)
// ===========================================================================
__global__ void __launch_bounds__(256) conv_split_kernel(
    const float* __restrict__ in, __half* __restrict__ out,
    int rows, int xmode)
{
    const int t = blockIdx.x * 256 + threadIdx.x;
    const int total = rows * (DM / 4);
    if (t >= total) return;
    const int r  = t / (DM / 4);
    const int c4 = (t - r * (DM / 4)) * 4;
    const float4 v = *(const float4*)&in[(size_t)r * DM + c4];

    __half2 h01 = __float22half2_rn(make_float2(v.x, v.y));
    __half2 h23 = __float22half2_rn(make_float2(v.z, v.w));
    float2 hf01 = __half22float2(h01);
    float2 hf23 = __half22float2(h23);
    __half2 l01 = __float22half2_rn(make_float2(v.x - hf01.x, v.y - hf01.y));
    __half2 l23 = __float22half2_rn(make_float2(v.z - hf23.x, v.w - hf23.y));

    uint2 hi, lo;
    hi.x = *(uint32_t*)&h01; hi.y = *(uint32_t*)&h23;
    lo.x = *(uint32_t*)&l01; lo.y = *(uint32_t*)&l23;

    __half* orow = out + (size_t)r * KCAT;
    *(uint2*)&orow[c4]      = hi;
    *(uint2*)&orow[DM + c4] = xmode ? lo : hi;
}

// conv_v: fp32 V -> per-(b,h) transposed fp16 Vt[64][SEQ] (hi only)
__global__ void __launch_bounds__(256) conv_v_kernel()
{
    __shared__ float vs[64][68];
    const int k0 = blockIdx.x * 64, h = blockIdx.y, b = blockIdx.z;
    const int tid = threadIdx.x;
#pragma unroll
    for (int t = 0; t < 4; t++) {
        const int u  = tid + t * 256;
        const int r  = u >> 4;
        const int c4 = (u & 15) * 4;
        *(float4*)&vs[r][c4] =
            *(const float4*)&g_V[(size_t)(b * SEQ + k0 + r) * DM + h * DKH + c4];
    }
    __syncthreads();
    const int d  = tid >> 2;
    const int kg = (tid & 3) * 16;
    uint4 hv[2];
    __half* hb = (__half*)hv;
#pragma unroll
    for (int i = 0; i < 16; i++)
        hb[i] = __float2half_rn(vs[kg + i][d]);
    __half* dhi = g_Vt + ((size_t)(b * NHEAD + h) * 64 + d) * SEQ + k0 + kg;
    *(uint4*)dhi = hv[0]; *((uint4*)dhi + 1) = hv[1];
}

// ===========================================================================
// Tensor-core GEMM: C = Xcat . Wcat^T + bias  (K = 1536)
// Epilogue modes: 0 = fp32 to C; 1 = per-head split fp16 [hi|lo] to Cc (Q);
//                 2 = per-head fp16 [hi|hi] to Cc (K).
// ===========================================================================
#define BKC       64
#define SM_STR    72
#define TILE_B    (128 * SM_STR * 2)
#define GS_TOTAL  (4 * TILE_B)               // 73728 B
#define NCHUNK    (KCAT / BKC)               // 24

__global__ void __launch_bounds__(256)
tc_gemm_kernel(const __half* __restrict__ Xc,
               const __half* __restrict__ Wc,
               const float* __restrict__ bias,
               float* __restrict__ C,
               __half* __restrict__ Cc,
               int mode)
{
    extern __shared__ char smem[];
    const uint32_t sbase = smem_u32(smem);
    const uint32_t aBuf[2] = { sbase,              sbase + TILE_B };
    const uint32_t bBuf[2] = { sbase + 2 * TILE_B, sbase + 3 * TILE_B };

    const int tid = threadIdx.x;
    const int wid = tid >> 5;
    const int L   = tid & 31;
    const int wm  = wid & 1;
    const int wn  = wid >> 1;
    const int bm0 = blockIdx.x * 128;
    const int bn0 = blockIdx.y * 128;

    const int aRow = (L & 7) + ((L >> 3) & 1) * 8;
    const int aK   = ((L >> 4) & 1) * 8;
    const int bRow = (L & 7) + ((L >> 4) & 1) * 8;
    const int bK   = ((L >> 3) & 1) * 8;
    const uint32_t aOff = ((wm * 64 + aRow) * SM_STR + aK) * 2;
    const uint32_t bOff = ((wn * 32 + bRow) * SM_STR + bK) * 2;

    float acc[4][4][4];
#pragma unroll
    for (int mt = 0; mt < 4; mt++)
#pragma unroll
        for (int nt = 0; nt < 4; nt++)
#pragma unroll
            for (int i = 0; i < 4; i++) acc[mt][nt][i] = 0.f;

    auto issue = [&](int c) {
        const int buf = c & 1;
#pragma unroll
        for (int t = 0; t < 4; t++) {
            const int u  = tid + t * 256;
            const int r  = u >> 3;
            const int c8 = (u & 7) * 8;
            cp16(aBuf[buf] + (r * SM_STR + c8) * 2,
                 &Xc[(size_t)(bm0 + r) * KCAT + c * BKC + c8]);
            cp16(bBuf[buf] + (r * SM_STR + c8) * 2,
                 &Wc[(size_t)(bn0 + r) * KCAT + c * BKC + c8]);
        }
        CP_COMMIT();
    };

    issue(0);
    for (int c = 0; c < NCHUNK; ++c) {
        const int buf = c & 1;
        if (c + 1 < NCHUNK) { issue(c + 1); CP_WAIT(1); }
        else                { CP_WAIT(0); }
        __syncthreads();
#pragma unroll
        for (int ks = 0; ks < 4; ++ks) {
            uint32_t af[4][4];
#pragma unroll
            for (int mt = 0; mt < 4; mt++)
                ldsm4(af[mt], aBuf[buf] + aOff + (mt * 16 * SM_STR + ks * 16) * 2);
            uint32_t bf[2][4];
#pragma unroll
            for (int np = 0; np < 2; np++)
                ldsm4(bf[np], bBuf[buf] + bOff + (np * 16 * SM_STR + ks * 16) * 2);
#pragma unroll
            for (int mt = 0; mt < 4; mt++)
#pragma unroll
                for (int nt = 0; nt < 4; nt++)
                    mma16816(acc[mt][nt], af[mt],
                             bf[nt >> 1][(nt & 1) * 2],
                             bf[nt >> 1][(nt & 1) * 2 + 1]);
        }
        __syncthreads();
    }

    const int qr = L >> 2;
    const int qc = (L & 3) * 2;
#pragma unroll
    for (int mt = 0; mt < 4; mt++) {
        const int row0 = bm0 + wm * 64 + mt * 16 + qr;
#pragma unroll
        for (int nt = 0; nt < 4; nt++) {
            const int col = bn0 + wn * 32 + nt * 8 + qc;
            const float2 bv = *(const float2*)&bias[col];
            const float* cc = acc[mt][nt];
            const float a0 = cc[0] + bv.x, a1 = cc[1] + bv.y;
            const float a2 = cc[2] + bv.x, a3 = cc[3] + bv.y;
            if (mode == 0) {
                *(float2*)&C[(size_t)row0 * DM + col]       = make_float2(a0, a1);
                *(float2*)&C[(size_t)(row0 + 8) * DM + col] = make_float2(a2, a3);
            } else {
                const int b = row0 >> 12, s = row0 & 4095;
                const int h = col >> 6, d = col & 63;
                __half* o0 = Cc + ((size_t)(b * NHEAD + h) * SEQ + s) * DC2;
                __half* o1 = o0 + 8 * DC2;
                uint32_t lo0, lo1;
                const uint32_t hi0 = pack_hl(a0, a1, lo0);
                const uint32_t hi1 = pack_hl(a2, a3, lo1);
                *(uint32_t*)&o0[d]      = hi0;
                *(uint32_t*)&o0[64 + d] = (mode == 1) ? lo0 : hi0;
                *(uint32_t*)&o1[d]      = hi1;
                *(uint32_t*)&o1[64 + d] = (mode == 1) ? lo1 : hi1;
            }
        }
    }
}

// ===========================================================================
// Tensor-core flash attention (2-seg QK, 2-pass PV) — unchanged from R8.
// CTA: 128 q-rows x one (b,h); 8 warps; k-tiles of 64; 2 CTAs/SM.
// Smem: Qs[128][136] | Ks[2][64][136] | Vts[2][64][72] | msk[2][64]
// ===========================================================================
#define QS_STR  136
#define VT_STR  72
#define KBUF    17408
#define VBUF    9216
#define AS_Q    0
#define AS_K    34816
#define AS_V    69632
#define AS_M    88064
#define AS_TOT  88576

__global__ void __launch_bounds__(256, 2)
attn_tc_kernel(const int* __restrict__ mask)
{
    extern __shared__ char sm[];
    const uint32_t sb = smem_u32(sm);
    const int tid = threadIdx.x;
    const int wid = tid >> 5;
    const int L   = tid & 31;
    const int qt  = gridDim.x - 1 - blockIdx.x;   // heavy tiles first
    const int h   = blockIdx.y;
    const int b   = blockIdx.z;
    const int q0  = qt * 128;
    const int nkt = 2 * (qt + 1);

    const __half* Qc = g_Qc + (size_t)(b * NHEAD + h) * SEQ * DC2;
    const __half* Kc = g_Kc + (size_t)(b * NHEAD + h) * SEQ * DC2;
    const __half* Vt = g_Vt + (size_t)(b * NHEAD + h) * 64 * SEQ;
    const int* mrow_g = mask + b * SEQ;

    // Prologue: Q tile (2048 x 16B) + stages 0,1.
#pragma unroll
    for (int t = 0; t < 8; t++) {
        const int u = tid + t * 256;
        const int r = u >> 4, c = u & 15;
        cp16(sb + AS_Q + (r * QS_STR + c * 8) * 2,
             Qc + (size_t)(q0 + r) * DC2 + c * 8);
    }
    auto issueKV = [&](int i) {
        const uint32_t kb = sb + AS_K + (i & 1) * KBUF;
        const uint32_t vb = sb + AS_V + (i & 1) * VBUF;
#pragma unroll
        for (int t = 0; t < 4; t++) {
            const int u = tid + t * 256;          // 1024 units
            const int r = u >> 4, c = u & 15;
            cp16(kb + (r * QS_STR + c * 8) * 2,
                 Kc + (size_t)(i * 64 + r) * DC2 + c * 8);
        }
#pragma unroll
        for (int t = 0; t < 2; t++) {
            const int u = tid + t * 256;          // 512 units
            const int r = u >> 3, c = u & 7;
            cp16(vb + (r * VT_STR + c * 8) * 2,
                 Vt + (size_t)r * SEQ + i * 64 + c * 8);
        }
        if (tid < 16)
            cp16(sb + AS_M + (i & 1) * 256 + tid * 16, mrow_g + i * 64 + tid * 4);
    };
    issueKV(0); CP_COMMIT();
    issueKV(1); CP_COMMIT();

    // Frag address components (same mapping as tc_gemm, validated).
    const int aRow = (L & 7) + ((L >> 3) & 1) * 8;
    const int aK   = ((L >> 4) & 1) * 8;
    const int bRow = (L & 7) + ((L >> 4) & 1) * 8;
    const int bK   = ((L >> 3) & 1) * 8;
    const uint32_t aBase = sb + AS_Q + ((wid * 16 + aRow) * QS_STR + aK) * 2;
    const int lr  = L >> 2;
    const int lc2 = (L & 3) * 2;
    const int r0  = q0 + wid * 16 + lr;

    float sO[8][4];
#pragma unroll
    for (int nd = 0; nd < 8; nd++)
#pragma unroll
        for (int i = 0; i < 4; i++) sO[nd][i] = 0.f;
    float m[2] = { -INFINITY, -INFINITY };
    float l[2] = { 0.f, 0.f };

    for (int kt = 0; kt < nkt; ++kt) {
        const int buf = kt & 1;
        const int k0  = kt * 64;
        CP_WAIT(1);
        __syncthreads();

        const uint32_t kBase = sb + AS_K + buf * KBUF + (bRow * QS_STR + bK) * 2;
        const uint32_t vBase = sb + AS_V + buf * VBUF + (bRow * VT_STR + bK) * 2;
        const int* msk = (const int*)(sm + AS_M + buf * 256);

        // ---- S = [Qhi|Qlo] . [Khi|Khi]^T over d=128 ----
        float sS[8][4];
#pragma unroll
        for (int nt = 0; nt < 8; nt++)
#pragma unroll
            for (int i = 0; i < 4; i++) sS[nt][i] = 0.f;
#pragma unroll
        for (int ks = 0; ks < 8; ++ks) {
            uint32_t af[4];
            ldsm4(af, aBase + ks * 32);
            uint32_t bf[4][4];
#pragma unroll
            for (int np = 0; np < 4; np++)
                ldsm4(bf[np], kBase + (np * 16 * QS_STR + ks * 16) * 2);
#pragma unroll
            for (int nt = 0; nt < 8; nt++)
                mma16816(sS[nt], af,
                         bf[nt >> 1][(nt & 1) * 2],
                         bf[nt >> 1][(nt & 1) * 2 + 1]);
        }

        // ---- scale + masks ----
        const bool dg = (kt + 2 >= nkt);
#pragma unroll
        for (int nt = 0; nt < 8; nt++) {
            const int cr = nt * 8 + lc2;
            const int cg = k0 + cr;
            const int m0 = msk[cr], m1 = msk[cr + 1];
            float v0 = sS[nt][0] * 0.125f, v1 = sS[nt][1] * 0.125f;
            float v2 = sS[nt][2] * 0.125f, v3 = sS[nt][3] * 0.125f;
            if (m0 == 0) { v0 = NEGINF; v2 = NEGINF; }
            if (m1 == 0) { v1 = NEGINF; v3 = NEGINF; }
            if (dg) {
                if (cg > r0)         v0 = NEGINF;
                if (cg + 1 > r0)     v1 = NEGINF;
                if (cg > r0 + 8)     v2 = NEGINF;
                if (cg + 1 > r0 + 8) v3 = NEGINF;
            }
            sS[nt][0] = v0; sS[nt][1] = v1; sS[nt][2] = v2; sS[nt][3] = v3;
        }

        // ---- online softmax (rows owned by 4-lane groups) ----
#pragma unroll
        for (int i = 0; i < 2; i++) {
            float rm = -INFINITY;
#pragma unroll
            for (int nt = 0; nt < 8; nt++)
                rm = fmaxf(rm, fmaxf(sS[nt][i * 2], sS[nt][i * 2 + 1]));
            rm = fmaxf(rm, __shfl_xor_sync(0xffffffffu, rm, 1));
            rm = fmaxf(rm, __shfl_xor_sync(0xffffffffu, rm, 2));
            const float mn   = fmaxf(m[i], rm);
            const float corr = __expf(m[i] - mn);
            float rs = 0.f;
#pragma unroll
            for (int nt = 0; nt < 8; nt++) {
                sS[nt][i * 2]     = __expf(sS[nt][i * 2] - mn);
                sS[nt][i * 2 + 1] = __expf(sS[nt][i * 2 + 1] - mn);
                rs += sS[nt][i * 2] + sS[nt][i * 2 + 1];
            }
            rs += __shfl_xor_sync(0xffffffffu, rs, 1);
            rs += __shfl_xor_sync(0xffffffffu, rs, 2);
            l[i] = l[i] * corr + rs;
            m[i] = mn;
#pragma unroll
            for (int nd = 0; nd < 8; nd++) {
                sO[nd][i * 2]     *= corr;
                sO[nd][i * 2 + 1] *= corr;
            }
        }

        // ---- O += (Phi+Plo).Vhi  (acc frags reused as PV A-frags) ----
#pragma unroll
        for (int t = 0; t < 4; t++) {
            uint32_t ah[4], al[4];
            ah[0] = pack_hl(sS[2 * t][0],     sS[2 * t][1],     al[0]);
            ah[1] = pack_hl(sS[2 * t][2],     sS[2 * t][3],     al[1]);
            ah[2] = pack_hl(sS[2 * t + 1][0], sS[2 * t + 1][1], al[2]);
            ah[3] = pack_hl(sS[2 * t + 1][2], sS[2 * t + 1][3], al[3]);
            uint32_t bv[4][4];
#pragma unroll
            for (int np = 0; np < 4; np++)
                ldsm4(bv[np], vBase + (np * 16 * VT_STR + t * 16) * 2);
#pragma unroll
            for (int nd = 0; nd < 8; nd++) {
                mma16816(sO[nd], ah, bv[nd >> 1][(nd & 1) * 2],
                         bv[nd >> 1][(nd & 1) * 2 + 1]);
                mma16816(sO[nd], al, bv[nd >> 1][(nd & 1) * 2],
                         bv[nd >> 1][(nd & 1) * 2 + 1]);
            }
        }

        __syncthreads();
        if (kt + 2 < nkt) issueKV(kt + 2);
        CP_COMMIT();
    }

    // ---- epilogue: normalize, write g_A[row][h*64 + d] ----
#pragma unroll
    for (int i = 0; i < 2; i++) {
        const float inv = 1.f / l[i];
        float* dst = g_A + ((size_t)b * SEQ + r0 + i * 8) * DM + h * DKH;
#pragma unroll
        for (int nd = 0; nd < 8; nd++)
            *(float2*)&dst[nd * 8 + lc2] =
                make_float2(sO[nd][i * 2] * inv, sO[nd][i * 2 + 1] * inv);
    }
}

// ===========================================================================
// Launch
// ===========================================================================
extern "C" void kernel_launch(void* const* d_in, const int* in_sizes, int n_in,
                              void* d_out, int out_size)
{
    const float* query = (const float*)d_in[0];
    const float* key   = (const float*)d_in[1];
    const float* value = (const float*)d_in[2];
    const int*   mask  = (const int*)  d_in[3];
    const float* Wq    = (const float*)d_in[4];
    const float* bq    = (const float*)d_in[5];
    const float* Wk    = (const float*)d_in[6];
    const float* bk    = (const float*)d_in[7];
    const float* Wv    = (const float*)d_in[8];
    const float* bv    = (const float*)d_in[9];
    const float* Wo    = (const float*)d_in[10];
    const float* bo    = (const float*)d_in[11];
    float* out = (float*)d_out;

    float *Vb, *Ab;
    __half *Xcat, *Wcat, *Qcp, *Kcp;
    cudaGetSymbolAddress((void**)&Vb, g_V);
    cudaGetSymbolAddress((void**)&Ab, g_A);
    cudaGetSymbolAddress((void**)&Xcat, g_Xcat);
    cudaGetSymbolAddress((void**)&Wcat, g_Wcat);
    cudaGetSymbolAddress((void**)&Qcp, g_Qc);
    cudaGetSymbolAddress((void**)&Kcp, g_Kc);

    cudaFuncSetAttribute(tc_gemm_kernel,
                         cudaFuncAttributeMaxDynamicSharedMemorySize, GS_TOTAL);
    cudaFuncSetAttribute(attn_tc_kernel,
                         cudaFuncAttributeMaxDynamicSharedMemorySize, AS_TOT);

    const int convX_blocks = (MROWS * (DM / 4) + 255) / 256;  // 6144
    const int convW_blocks = (DM * (DM / 4) + 255) / 256;     // 576
    const dim3 ggrid(MROWS / 128, DM / 128);                  // (64, 6)

    // Q projection -> g_Qc directly (split [hi|lo])
    conv_split_kernel<<<convX_blocks, 256>>>(query, Xcat, MROWS, 1);
    conv_split_kernel<<<convW_blocks, 256>>>(Wq, Wcat, DM, 0);
    tc_gemm_kernel<<<ggrid, 256, GS_TOTAL>>>(Xcat, Wcat, bq, nullptr, Qcp, 1);
    // K projection -> g_Kc directly ([hi|hi])
    conv_split_kernel<<<convX_blocks, 256>>>(key, Xcat, MROWS, 1);
    conv_split_kernel<<<convW_blocks, 256>>>(Wk, Wcat, DM, 0);
    tc_gemm_kernel<<<ggrid, 256, GS_TOTAL>>>(Xcat, Wcat, bk, nullptr, Kcp, 2);
    // V projection -> fp32 g_V, then transpose/convert (hi only)
    conv_split_kernel<<<convX_blocks, 256>>>(value, Xcat, MROWS, 1);
    conv_split_kernel<<<convW_blocks, 256>>>(Wv, Wcat, DM, 0);
    tc_gemm_kernel<<<ggrid, 256, GS_TOTAL>>>(Xcat, Wcat, bv, Vb, nullptr, 0);
    conv_v_kernel<<<dim3(SEQ / 64, NHEAD, BATCH), 256>>>();

    // Tensor-core flash attention
    attn_tc_kernel<<<dim3(SEQ / 128, NHEAD, BATCH), 256, AS_TOT>>>(mask);

    // Output projection
    conv_split_kernel<<<convX_blocks, 256>>>(Ab, Xcat, MROWS, 1);
    conv_split_kernel<<<convW_blocks, 256>>>(Wo, Wcat, DM, 0);
    tc_gemm_kernel<<<ggrid, 256, GS_TOTAL>>>(Xcat, Wcat, bo, out, nullptr, 0);
}

// round 16
// speedup vs baseline: 3.8327x; 1.0891x over previous
#include <cuda_runtime.h>
#include <cuda_fp16.h>
#include <math.h>
#include <stdint.h>

// Problem constants (fixed by the reference).
#define BATCH   2
#define SEQ     4096
#define DM      768
#define NHEAD   12
#define DKH     64
#define MROWS   (BATCH * SEQ)   // 8192
#define KCAT    (2 * DM)        // 1536: X=[hi|lo], W=[hi|hi]  ->  X . fp16(W)^T
#define DC2     128             // 2-seg concat head dim for QK
#define NEGINF  (-1e9f)

// Scratch (allocation-free: __device__ globals).
__device__ float g_V[MROWS * DM];
__device__ float g_A[MROWS * DM];
__device__ __half g_Xcat[(size_t)MROWS * KCAT];             // 25.2 MB
__device__ __half g_Wcat[(size_t)DM * KCAT];                // 2.25 MB
__device__ __half g_Qc[(size_t)BATCH * NHEAD * SEQ * DC2];  // 25.2 MB [hi|lo]
__device__ __half g_Kc[(size_t)BATCH * NHEAD * SEQ * DC2];  // 25.2 MB [hi|hi]
__device__ __half g_Vt[(size_t)BATCH * NHEAD * 64 * SEQ];   // 12.6 MB (hi only)

// ===========================================================================
// Warp-MMA helpers (sm_80+ path, legal on plain sm_103)
// ===========================================================================
__device__ __forceinline__ uint32_t smem_u32(const void* p) {
    uint32_t a;
    asm("{ .reg .u64 t; cvta.to.shared.u64 t, %1; cvt.u32.u64 %0, t; }"
        : "=r"(a) : "l"(p));
    return a;
}
__device__ __forceinline__ void ldsm4(uint32_t* r, uint32_t addr) {
    asm volatile("ldmatrix.sync.aligned.m8n8.x4.shared.b16 {%0,%1,%2,%3}, [%4];"
                 : "=r"(r[0]), "=r"(r[1]), "=r"(r[2]), "=r"(r[3]) : "r"(addr));
}
__device__ __forceinline__ void mma16816(float* c, const uint32_t* a,
                                         uint32_t b0, uint32_t b1) {
    asm volatile(
        "mma.sync.aligned.m16n8k16.row.col.f32.f16.f16.f32 "
        "{%0,%1,%2,%3}, {%4,%5,%6,%7}, {%8,%9}, {%0,%1,%2,%3};"
        : "+f"(c[0]), "+f"(c[1]), "+f"(c[2]), "+f"(c[3])
        : "r"(a[0]), "r"(a[1]), "r"(a[2]), "r"(a[3]), "r"(b0), "r"(b1));
}
__device__ __forceinline__ void cp16(uint32_t dst, const void* src) {
    asm volatile("cp.async.cg.shared.global [%0], [%1], 16;"
                 :: "r"(dst), "l"(src));
}
#define CP_COMMIT() asm volatile("cp.async.commit_group;" ::: "memory")
#define CP_WAIT(n)  asm volatile("cp.async.wait_group %0;" :: "n"(n) : "memory")

__device__ __forceinline__ uint32_t pack_hl(float a, float b, uint32_t& lo) {
    __half ha = __float2half_rn(a), hb = __float2half_rn(b);
    __half la = __float2half_rn(a - __half2float(ha));
    __half lb = __float2half_rn(b - __half2float(hb));
    __half2 hh = __halves2half2(ha, hb);
    __half2 ll = __halves2half2(la, lb);
    lo = *(uint32_t*)&ll;
    return *(uint32_t*)&hh;
}
__device__ __forceinline__ uint32_t pack2(float a, float b) {
    __half2 hh = __float22half2_rn(make_float2(a, b));
    return *(uint32_t*)&hh;
}

// ===========================================================================
// Split conversion for projections: fp32 [rows x 768] -> fp16 [rows x 1536]
// xmode=1: [hi | lo]  (activations: exact to 22 bits)
// xmode=0: [hi | hi]  (weights: fp16-rounded)
// ===========================================================================
__global__ void __launch_bounds__(256) conv_split_kernel(
    const float* __restrict__ in, __half* __restrict__ out,
    int rows, int xmode)
{
    const int t = blockIdx.x * 256 + threadIdx.x;
    const int total = rows * (DM / 4);
    if (t >= total) return;
    const int r  = t / (DM / 4);
    const int c4 = (t - r * (DM / 4)) * 4;
    const float4 v = *(const float4*)&in[(size_t)r * DM + c4];

    __half2 h01 = __float22half2_rn(make_float2(v.x, v.y));
    __half2 h23 = __float22half2_rn(make_float2(v.z, v.w));
    float2 hf01 = __half22float2(h01);
    float2 hf23 = __half22float2(h23);
    __half2 l01 = __float22half2_rn(make_float2(v.x - hf01.x, v.y - hf01.y));
    __half2 l23 = __float22half2_rn(make_float2(v.z - hf23.x, v.w - hf23.y));

    uint2 hi, lo;
    hi.x = *(uint32_t*)&h01; hi.y = *(uint32_t*)&h23;
    lo.x = *(uint32_t*)&l01; lo.y = *(uint32_t*)&l23;

    __half* orow = out + (size_t)r * KCAT;
    *(uint2*)&orow[c4]      = hi;
    *(uint2*)&orow[DM + c4] = xmode ? lo : hi;
}

// conv_v: fp32 V -> per-(b,h) transposed fp16 Vt[64][SEQ] (hi only)
__global__ void __launch_bounds__(256) conv_v_kernel()
{
    __shared__ float vs[64][68];
    const int k0 = blockIdx.x * 64, h = blockIdx.y, b = blockIdx.z;
    const int tid = threadIdx.x;
#pragma unroll
    for (int t = 0; t < 4; t++) {
        const int u  = tid + t * 256;
        const int r  = u >> 4;
        const int c4 = (u & 15) * 4;
        *(float4*)&vs[r][c4] =
            *(const float4*)&g_V[(size_t)(b * SEQ + k0 + r) * DM + h * DKH + c4];
    }
    __syncthreads();
    const int d  = tid >> 2;
    const int kg = (tid & 3) * 16;
    uint4 hv[2];
    __half* hb = (__half*)hv;
#pragma unroll
    for (int i = 0; i < 16; i++)
        hb[i] = __float2half_rn(vs[kg + i][d]);
    __half* dhi = g_Vt + ((size_t)(b * NHEAD + h) * 64 + d) * SEQ + k0 + kg;
    *(uint4*)dhi = hv[0]; *((uint4*)dhi + 1) = hv[1];
}

// ===========================================================================
// Tensor-core GEMM: C = Xcat . Wcat^T + bias  (K = 1536)
// Epilogue modes: 0 = fp32 to C; 1 = per-head split fp16 [hi|lo] to Cc (Q);
//                 2 = per-head fp16 [hi|hi] to Cc (K).
// ===========================================================================
#define BKC       64
#define SM_STR    72
#define TILE_B    (128 * SM_STR * 2)
#define GS_TOTAL  (4 * TILE_B)               // 73728 B
#define NCHUNK    (KCAT / BKC)               // 24

__global__ void __launch_bounds__(256)
tc_gemm_kernel(const __half* __restrict__ Xc,
               const __half* __restrict__ Wc,
               const float* __restrict__ bias,
               float* __restrict__ C,
               __half* __restrict__ Cc,
               int mode)
{
    extern __shared__ char smem[];
    const uint32_t sbase = smem_u32(smem);
    const uint32_t aBuf[2] = { sbase,              sbase + TILE_B };
    const uint32_t bBuf[2] = { sbase + 2 * TILE_B, sbase + 3 * TILE_B };

    const int tid = threadIdx.x;
    const int wid = tid >> 5;
    const int L   = tid & 31;
    const int wm  = wid & 1;
    const int wn  = wid >> 1;
    const int bm0 = blockIdx.x * 128;
    const int bn0 = blockIdx.y * 128;

    const int aRow = (L & 7) + ((L >> 3) & 1) * 8;
    const int aK   = ((L >> 4) & 1) * 8;
    const int bRow = (L & 7) + ((L >> 4) & 1) * 8;
    const int bK   = ((L >> 3) & 1) * 8;
    const uint32_t aOff = ((wm * 64 + aRow) * SM_STR + aK) * 2;
    const uint32_t bOff = ((wn * 32 + bRow) * SM_STR + bK) * 2;

    float acc[4][4][4];
#pragma unroll
    for (int mt = 0; mt < 4; mt++)
#pragma unroll
        for (int nt = 0; nt < 4; nt++)
#pragma unroll
            for (int i = 0; i < 4; i++) acc[mt][nt][i] = 0.f;

    auto issue = [&](int c) {
        const int buf = c & 1;
#pragma unroll
        for (int t = 0; t < 4; t++) {
            const int u  = tid + t * 256;
            const int r  = u >> 3;
            const int c8 = (u & 7) * 8;
            cp16(aBuf[buf] + (r * SM_STR + c8) * 2,
                 &Xc[(size_t)(bm0 + r) * KCAT + c * BKC + c8]);
            cp16(bBuf[buf] + (r * SM_STR + c8) * 2,
                 &Wc[(size_t)(bn0 + r) * KCAT + c * BKC + c8]);
        }
        CP_COMMIT();
    };

    issue(0);
    for (int c = 0; c < NCHUNK; ++c) {
        const int buf = c & 1;
        if (c + 1 < NCHUNK) { issue(c + 1); CP_WAIT(1); }
        else                { CP_WAIT(0); }
        __syncthreads();
#pragma unroll
        for (int ks = 0; ks < 4; ++ks) {
            uint32_t af[4][4];
#pragma unroll
            for (int mt = 0; mt < 4; mt++)
                ldsm4(af[mt], aBuf[buf] + aOff + (mt * 16 * SM_STR + ks * 16) * 2);
            uint32_t bf[2][4];
#pragma unroll
            for (int np = 0; np < 2; np++)
                ldsm4(bf[np], bBuf[buf] + bOff + (np * 16 * SM_STR + ks * 16) * 2);
#pragma unroll
            for (int mt = 0; mt < 4; mt++)
#pragma unroll
                for (int nt = 0; nt < 4; nt++)
                    mma16816(acc[mt][nt], af[mt],
                             bf[nt >> 1][(nt & 1) * 2],
                             bf[nt >> 1][(nt & 1) * 2 + 1]);
        }
        __syncthreads();
    }

    const int qr = L >> 2;
    const int qc = (L & 3) * 2;
#pragma unroll
    for (int mt = 0; mt < 4; mt++) {
        const int row0 = bm0 + wm * 64 + mt * 16 + qr;
#pragma unroll
        for (int nt = 0; nt < 4; nt++) {
            const int col = bn0 + wn * 32 + nt * 8 + qc;
            const float2 bv = *(const float2*)&bias[col];
            const float* cc = acc[mt][nt];
            const float a0 = cc[0] + bv.x, a1 = cc[1] + bv.y;
            const float a2 = cc[2] + bv.x, a3 = cc[3] + bv.y;
            if (mode == 0) {
                *(float2*)&C[(size_t)row0 * DM + col]       = make_float2(a0, a1);
                *(float2*)&C[(size_t)(row0 + 8) * DM + col] = make_float2(a2, a3);
            } else {
                const int b = row0 >> 12, s = row0 & 4095;
                const int h = col >> 6, d = col & 63;
                __half* o0 = Cc + ((size_t)(b * NHEAD + h) * SEQ + s) * DC2;
                __half* o1 = o0 + 8 * DC2;
                uint32_t lo0, lo1;
                const uint32_t hi0 = pack_hl(a0, a1, lo0);
                const uint32_t hi1 = pack_hl(a2, a3, lo1);
                *(uint32_t*)&o0[d]      = hi0;
                *(uint32_t*)&o0[64 + d] = (mode == 1) ? lo0 : hi0;
                *(uint32_t*)&o1[d]      = hi1;
                *(uint32_t*)&o1[64 + d] = (mode == 1) ? lo1 : hi1;
            }
        }
    }
}

// ===========================================================================
// Tensor-core flash attention (2-seg QK, 1-pass fp16 PV).
// CTA: 128 q-rows x one (b,h); 8 warps; k-tiles of 64; 2 CTAs/SM.
// Smem: Qs[128][136] | Ks[2][64][136] | Vts[2][64][72] | msk[2][64]
// ===========================================================================
#define QS_STR  136
#define VT_STR  72
#define KBUF    17408
#define VBUF    9216
#define AS_Q    0
#define AS_K    34816
#define AS_V    69632
#define AS_M    88064
#define AS_TOT  88576

__global__ void __launch_bounds__(256, 2)
attn_tc_kernel(const int* __restrict__ mask)
{
    extern __shared__ char sm[];
    const uint32_t sb = smem_u32(sm);
    const int tid = threadIdx.x;
    const int wid = tid >> 5;
    const int L   = tid & 31;
    const int qt  = gridDim.x - 1 - blockIdx.x;   // heavy tiles first
    const int h   = blockIdx.y;
    const int b   = blockIdx.z;
    const int q0  = qt * 128;
    const int nkt = 2 * (qt + 1);

    const __half* Qc = g_Qc + (size_t)(b * NHEAD + h) * SEQ * DC2;
    const __half* Kc = g_Kc + (size_t)(b * NHEAD + h) * SEQ * DC2;
    const __half* Vt = g_Vt + (size_t)(b * NHEAD + h) * 64 * SEQ;
    const int* mrow_g = mask + b * SEQ;

    // Prologue: Q tile (2048 x 16B) + stages 0,1.
#pragma unroll
    for (int t = 0; t < 8; t++) {
        const int u = tid + t * 256;
        const int r = u >> 4, c = u & 15;
        cp16(sb + AS_Q + (r * QS_STR + c * 8) * 2,
             Qc + (size_t)(q0 + r) * DC2 + c * 8);
    }
    auto issueKV = [&](int i) {
        const uint32_t kb = sb + AS_K + (i & 1) * KBUF;
        const uint32_t vb = sb + AS_V + (i & 1) * VBUF;
#pragma unroll
        for (int t = 0; t < 4; t++) {
            const int u = tid + t * 256;          // 1024 units
            const int r = u >> 4, c = u & 15;
            cp16(kb + (r * QS_STR + c * 8) * 2,
                 Kc + (size_t)(i * 64 + r) * DC2 + c * 8);
        }
#pragma unroll
        for (int t = 0; t < 2; t++) {
            const int u = tid + t * 256;          // 512 units
            const int r = u >> 3, c = u & 7;
            cp16(vb + (r * VT_STR + c * 8) * 2,
                 Vt + (size_t)r * SEQ + i * 64 + c * 8);
        }
        if (tid < 16)
            cp16(sb + AS_M + (i & 1) * 256 + tid * 16, mrow_g + i * 64 + tid * 4);
    };
    issueKV(0); CP_COMMIT();
    issueKV(1); CP_COMMIT();

    // Frag address components (same mapping as tc_gemm, validated).
    const int aRow = (L & 7) + ((L >> 3) & 1) * 8;
    const int aK   = ((L >> 4) & 1) * 8;
    const int bRow = (L & 7) + ((L >> 4) & 1) * 8;
    const int bK   = ((L >> 3) & 1) * 8;
    const uint32_t aBase = sb + AS_Q + ((wid * 16 + aRow) * QS_STR + aK) * 2;
    const int lr  = L >> 2;
    const int lc2 = (L & 3) * 2;
    const int r0  = q0 + wid * 16 + lr;

    float sO[8][4];
#pragma unroll
    for (int nd = 0; nd < 8; nd++)
#pragma unroll
        for (int i = 0; i < 4; i++) sO[nd][i] = 0.f;
    float m[2] = { -INFINITY, -INFINITY };
    float l[2] = { 0.f, 0.f };

    for (int kt = 0; kt < nkt; ++kt) {
        const int buf = kt & 1;
        const int k0  = kt * 64;
        CP_WAIT(1);
        __syncthreads();

        const uint32_t kBase = sb + AS_K + buf * KBUF + (bRow * QS_STR + bK) * 2;
        const uint32_t vBase = sb + AS_V + buf * VBUF + (bRow * VT_STR + bK) * 2;
        const int* msk = (const int*)(sm + AS_M + buf * 256);

        // ---- S = [Qhi|Qlo] . [Khi|Khi]^T over d=128 ----
        float sS[8][4];
#pragma unroll
        for (int nt = 0; nt < 8; nt++)
#pragma unroll
            for (int i = 0; i < 4; i++) sS[nt][i] = 0.f;
#pragma unroll
        for (int ks = 0; ks < 8; ++ks) {
            uint32_t af[4];
            ldsm4(af, aBase + ks * 32);
            uint32_t bf[4][4];
#pragma unroll
            for (int np = 0; np < 4; np++)
                ldsm4(bf[np], kBase + (np * 16 * QS_STR + ks * 16) * 2);
#pragma unroll
            for (int nt = 0; nt < 8; nt++)
                mma16816(sS[nt], af,
                         bf[nt >> 1][(nt & 1) * 2],
                         bf[nt >> 1][(nt & 1) * 2 + 1]);
        }

        // ---- scale + masks ----
        const bool dg = (kt + 2 >= nkt);
#pragma unroll
        for (int nt = 0; nt < 8; nt++) {
            const int cr = nt * 8 + lc2;
            const int cg = k0 + cr;
            const int m0 = msk[cr], m1 = msk[cr + 1];
            float v0 = sS[nt][0] * 0.125f, v1 = sS[nt][1] * 0.125f;
            float v2 = sS[nt][2] * 0.125f, v3 = sS[nt][3] * 0.125f;
            if (m0 == 0) { v0 = NEGINF; v2 = NEGINF; }
            if (m1 == 0) { v1 = NEGINF; v3 = NEGINF; }
            if (dg) {
                if (cg > r0)         v0 = NEGINF;
                if (cg + 1 > r0)     v1 = NEGINF;
                if (cg > r0 + 8)     v2 = NEGINF;
                if (cg + 1 > r0 + 8) v3 = NEGINF;
            }
            sS[nt][0] = v0; sS[nt][1] = v1; sS[nt][2] = v2; sS[nt][3] = v3;
        }

        // ---- online softmax (rows owned by 4-lane groups) ----
#pragma unroll
        for (int i = 0; i < 2; i++) {
            float rm = -INFINITY;
#pragma unroll
            for (int nt = 0; nt < 8; nt++)
                rm = fmaxf(rm, fmaxf(sS[nt][i * 2], sS[nt][i * 2 + 1]));
            rm = fmaxf(rm, __shfl_xor_sync(0xffffffffu, rm, 1));
            rm = fmaxf(rm, __shfl_xor_sync(0xffffffffu, rm, 2));
            const float mn   = fmaxf(m[i], rm);
            const float corr = __expf(m[i] - mn);
            float rs = 0.f;
#pragma unroll
            for (int nt = 0; nt < 8; nt++) {
                sS[nt][i * 2]     = __expf(sS[nt][i * 2] - mn);
                sS[nt][i * 2 + 1] = __expf(sS[nt][i * 2 + 1] - mn);
                rs += sS[nt][i * 2] + sS[nt][i * 2 + 1];
            }
            rs += __shfl_xor_sync(0xffffffffu, rs, 1);
            rs += __shfl_xor_sync(0xffffffffu, rs, 2);
            l[i] = l[i] * corr + rs;
            m[i] = mn;
#pragma unroll
            for (int nd = 0; nd < 8; nd++) {
                sO[nd][i * 2]     *= corr;
                sO[nd][i * 2 + 1] *= corr;
            }
        }

        // ---- O += fp16(P).Vhi  (1-pass; acc frags reused as PV A-frags) ----
#pragma unroll
        for (int t = 0; t < 4; t++) {
            uint32_t ah[4];
            ah[0] = pack2(sS[2 * t][0],     sS[2 * t][1]);
            ah[1] = pack2(sS[2 * t][2],     sS[2 * t][3]);
            ah[2] = pack2(sS[2 * t + 1][0], sS[2 * t + 1][1]);
            ah[3] = pack2(sS[2 * t + 1][2], sS[2 * t + 1][3]);
            uint32_t bv[4][4];
#pragma unroll
            for (int np = 0; np < 4; np++)
                ldsm4(bv[np], vBase + (np * 16 * VT_STR + t * 16) * 2);
#pragma unroll
            for (int nd = 0; nd < 8; nd++)
                mma16816(sO[nd], ah, bv[nd >> 1][(nd & 1) * 2],
                         bv[nd >> 1][(nd & 1) * 2 + 1]);
        }

        __syncthreads();
        if (kt + 2 < nkt) issueKV(kt + 2);
        CP_COMMIT();
    }

    // ---- epilogue: normalize, write g_A[row][h*64 + d] ----
#pragma unroll
    for (int i = 0; i < 2; i++) {
        const float inv = 1.f / l[i];
        float* dst = g_A + ((size_t)b * SEQ + r0 + i * 8) * DM + h * DKH;
#pragma unroll
        for (int nd = 0; nd < 8; nd++)
            *(float2*)&dst[nd * 8 + lc2] =
                make_float2(sO[nd][i * 2] * inv, sO[nd][i * 2 + 1] * inv);
    }
}

// ===========================================================================
// Launch
// ===========================================================================
extern "C" void kernel_launch(void* const* d_in, const int* in_sizes, int n_in,
                              void* d_out, int out_size)
{
    const float* query = (const float*)d_in[0];
    const float* key   = (const float*)d_in[1];
    const float* value = (const float*)d_in[2];
    const int*   mask  = (const int*)  d_in[3];
    const float* Wq    = (const float*)d_in[4];
    const float* bq    = (const float*)d_in[5];
    const float* Wk    = (const float*)d_in[6];
    const float* bk    = (const float*)d_in[7];
    const float* Wv    = (const float*)d_in[8];
    const float* bv    = (const float*)d_in[9];
    const float* Wo    = (const float*)d_in[10];
    const float* bo    = (const float*)d_in[11];
    float* out = (float*)d_out;

    float *Vb, *Ab;
    __half *Xcat, *Wcat, *Qcp, *Kcp;
    cudaGetSymbolAddress((void**)&Vb, g_V);
    cudaGetSymbolAddress((void**)&Ab, g_A);
    cudaGetSymbolAddress((void**)&Xcat, g_Xcat);
    cudaGetSymbolAddress((void**)&Wcat, g_Wcat);
    cudaGetSymbolAddress((void**)&Qcp, g_Qc);
    cudaGetSymbolAddress((void**)&Kcp, g_Kc);

    cudaFuncSetAttribute(tc_gemm_kernel,
                         cudaFuncAttributeMaxDynamicSharedMemorySize, GS_TOTAL);
    cudaFuncSetAttribute(attn_tc_kernel,
                         cudaFuncAttributeMaxDynamicSharedMemorySize, AS_TOT);

    const int convX_blocks = (MROWS * (DM / 4) + 255) / 256;  // 6144
    const int convW_blocks = (DM * (DM / 4) + 255) / 256;     // 576
    const dim3 ggrid(MROWS / 128, DM / 128);                  // (64, 6)

    // Q projection -> g_Qc directly (split [hi|lo])
    conv_split_kernel<<<convX_blocks, 256>>>(query, Xcat, MROWS, 1);
    conv_split_kernel<<<convW_blocks, 256>>>(Wq, Wcat, DM, 0);
    tc_gemm_kernel<<<ggrid, 256, GS_TOTAL>>>(Xcat, Wcat, bq, nullptr, Qcp, 1);
    // K projection -> g_Kc directly ([hi|hi])
    conv_split_kernel<<<convX_blocks, 256>>>(key, Xcat, MROWS, 1);
    conv_split_kernel<<<convW_blocks, 256>>>(Wk, Wcat, DM, 0);
    tc_gemm_kernel<<<ggrid, 256, GS_TOTAL>>>(Xcat, Wcat, bk, nullptr, Kcp, 2);
    // V projection -> fp32 g_V, then transpose/convert (hi only)
    conv_split_kernel<<<convX_blocks, 256>>>(value, Xcat, MROWS, 1);
    conv_split_kernel<<<convW_blocks, 256>>>(Wv, Wcat, DM, 0);
    tc_gemm_kernel<<<ggrid, 256, GS_TOTAL>>>(Xcat, Wcat, bv, Vb, nullptr, 0);
    conv_v_kernel<<<dim3(SEQ / 64, NHEAD, BATCH), 256>>>();

    // Tensor-core flash attention
    attn_tc_kernel<<<dim3(SEQ / 128, NHEAD, BATCH), 256, AS_TOT>>>(mask);

    // Output projection
    conv_split_kernel<<<convX_blocks, 256>>>(Ab, Xcat, MROWS, 1);
    conv_split_kernel<<<convW_blocks, 256>>>(Wo, Wcat, DM, 0);
    tc_gemm_kernel<<<ggrid, 256, GS_TOTAL>>>(Xcat, Wcat, bo, out, nullptr, 0);
}

// round 17
// speedup vs baseline: 4.7256x; 1.2330x over previous
#include <cuda_runtime.h>
#include <cuda_fp16.h>
#include <math.h>
#include <stdint.h>

// Problem constants (fixed by the reference).
#define BATCH   2
#define SEQ     4096
#define DM      768
#define NHEAD   12
#define DKH     64
#define MROWS   (BATCH * SEQ)   // 8192
#define KCAT    DM              // 768: plain fp16 X . fp16(W)^T
#define DC2     128             // 2-seg concat head dim for QK
#define NEGINF  (-1e9f)

// Scratch (allocation-free: __device__ globals).
__device__ float g_V[MROWS * DM];
__device__ float g_A[MROWS * DM];
__device__ __half g_Xcat[(size_t)MROWS * KCAT];             // 12.6 MB
__device__ __half g_Wcat[(size_t)DM * KCAT];                // 1.1 MB
__device__ __half g_Qc[(size_t)BATCH * NHEAD * SEQ * DC2];  // 25.2 MB [hi|lo]
__device__ __half g_Kc[(size_t)BATCH * NHEAD * SEQ * DC2];  // 25.2 MB [hi|hi]
__device__ __half g_Vt[(size_t)BATCH * NHEAD * 64 * SEQ];   // 12.6 MB (hi only)

// ===========================================================================
// Warp-MMA helpers (sm_80+ path, legal on plain sm_103)
// ===========================================================================
__device__ __forceinline__ uint32_t smem_u32(const void* p) {
    uint32_t a;
    asm("{ .reg .u64 t; cvta.to.shared.u64 t, %1; cvt.u32.u64 %0, t; }"
        : "=r"(a) : "l"(p));
    return a;
}
__device__ __forceinline__ void ldsm4(uint32_t* r, uint32_t addr) {
    asm volatile("ldmatrix.sync.aligned.m8n8.x4.shared.b16 {%0,%1,%2,%3}, [%4];"
                 : "=r"(r[0]), "=r"(r[1]), "=r"(r[2]), "=r"(r[3]) : "r"(addr));
}
__device__ __forceinline__ void mma16816(float* c, const uint32_t* a,
                                         uint32_t b0, uint32_t b1) {
    asm volatile(
        "mma.sync.aligned.m16n8k16.row.col.f32.f16.f16.f32 "
        "{%0,%1,%2,%3}, {%4,%5,%6,%7}, {%8,%9}, {%0,%1,%2,%3};"
        : "+f"(c[0]), "+f"(c[1]), "+f"(c[2]), "+f"(c[3])
        : "r"(a[0]), "r"(a[1]), "r"(a[2]), "r"(a[3]), "r"(b0), "r"(b1));
}
__device__ __forceinline__ void cp16(uint32_t dst, const void* src) {
    asm volatile("cp.async.cg.shared.global [%0], [%1], 16;"
                 :: "r"(dst), "l"(src));
}
#define CP_COMMIT() asm volatile("cp.async.commit_group;" ::: "memory")
#define CP_WAIT(n)  asm volatile("cp.async.wait_group %0;" :: "n"(n) : "memory")

__device__ __forceinline__ uint32_t pack_hl(float a, float b, uint32_t& lo) {
    __half ha = __float2half_rn(a), hb = __float2half_rn(b);
    __half la = __float2half_rn(a - __half2float(ha));
    __half lb = __float2half_rn(b - __half2float(hb));
    __half2 hh = __halves2half2(ha, hb);
    __half2 ll = __halves2half2(la, lb);
    lo = *(uint32_t*)&ll;
    return *(uint32_t*)&hh;
}
__device__ __forceinline__ uint32_t pack2(float a, float b) {
    __half2 hh = __float22half2_rn(make_float2(a, b));
    return *(uint32_t*)&hh;
}

// ===========================================================================
// Plain fp16 conversion: fp32 [rows x 768] -> fp16 [rows x 768]
// ===========================================================================
__global__ void __launch_bounds__(256) conv_fp16_kernel(
    const float* __restrict__ in, __half* __restrict__ out, int rows)
{
    const int t = blockIdx.x * 256 + threadIdx.x;
    const int total = rows * (DM / 4);
    if (t >= total) return;
    const float4 v = *(const float4*)&in[(size_t)t * 4];
    __half2 h01 = __float22half2_rn(make_float2(v.x, v.y));
    __half2 h23 = __float22half2_rn(make_float2(v.z, v.w));
    uint2 hi;
    hi.x = *(uint32_t*)&h01; hi.y = *(uint32_t*)&h23;
    *(uint2*)&out[(size_t)t * 4] = hi;
}

// conv_v: fp32 V -> per-(b,h) transposed fp16 Vt[64][SEQ] (hi only)
__global__ void __launch_bounds__(256) conv_v_kernel()
{
    __shared__ float vs[64][68];
    const int k0 = blockIdx.x * 64, h = blockIdx.y, b = blockIdx.z;
    const int tid = threadIdx.x;
#pragma unroll
    for (int t = 0; t < 4; t++) {
        const int u  = tid + t * 256;
        const int r  = u >> 4;
        const int c4 = (u & 15) * 4;
        *(float4*)&vs[r][c4] =
            *(const float4*)&g_V[(size_t)(b * SEQ + k0 + r) * DM + h * DKH + c4];
    }
    __syncthreads();
    const int d  = tid >> 2;
    const int kg = (tid & 3) * 16;
    uint4 hv[2];
    __half* hb = (__half*)hv;
#pragma unroll
    for (int i = 0; i < 16; i++)
        hb[i] = __float2half_rn(vs[kg + i][d]);
    __half* dhi = g_Vt + ((size_t)(b * NHEAD + h) * 64 + d) * SEQ + k0 + kg;
    *(uint4*)dhi = hv[0]; *((uint4*)dhi + 1) = hv[1];
}

// ===========================================================================
// Tensor-core GEMM: C = Xcat . Wcat^T + bias  (K = 768, plain fp16)
// Epilogue modes: 0 = fp32 to C; 1 = per-head split fp16 [hi|lo] to Cc (Q);
//                 2 = per-head fp16 [hi|hi] to Cc (K).
// ===========================================================================
#define BKC       64
#define SM_STR    72
#define TILE_B    (128 * SM_STR * 2)
#define GS_TOTAL  (4 * TILE_B)               // 73728 B
#define NCHUNK    (KCAT / BKC)               // 12

__global__ void __launch_bounds__(256)
tc_gemm_kernel(const __half* __restrict__ Xc,
               const __half* __restrict__ Wc,
               const float* __restrict__ bias,
               float* __restrict__ C,
               __half* __restrict__ Cc,
               int mode)
{
    extern __shared__ char smem[];
    const uint32_t sbase = smem_u32(smem);
    const uint32_t aBuf[2] = { sbase,              sbase + TILE_B };
    const uint32_t bBuf[2] = { sbase + 2 * TILE_B, sbase + 3 * TILE_B };

    const int tid = threadIdx.x;
    const int wid = tid >> 5;
    const int L   = tid & 31;
    const int wm  = wid & 1;
    const int wn  = wid >> 1;
    const int bm0 = blockIdx.x * 128;
    const int bn0 = blockIdx.y * 128;

    const int aRow = (L & 7) + ((L >> 3) & 1) * 8;
    const int aK   = ((L >> 4) & 1) * 8;
    const int bRow = (L & 7) + ((L >> 4) & 1) * 8;
    const int bK   = ((L >> 3) & 1) * 8;
    const uint32_t aOff = ((wm * 64 + aRow) * SM_STR + aK) * 2;
    const uint32_t bOff = ((wn * 32 + bRow) * SM_STR + bK) * 2;

    float acc[4][4][4];
#pragma unroll
    for (int mt = 0; mt < 4; mt++)
#pragma unroll
        for (int nt = 0; nt < 4; nt++)
#pragma unroll
            for (int i = 0; i < 4; i++) acc[mt][nt][i] = 0.f;

    auto issue = [&](int c) {
        const int buf = c & 1;
#pragma unroll
        for (int t = 0; t < 4; t++) {
            const int u  = tid + t * 256;
            const int r  = u >> 3;
            const int c8 = (u & 7) * 8;
            cp16(aBuf[buf] + (r * SM_STR + c8) * 2,
                 &Xc[(size_t)(bm0 + r) * KCAT + c * BKC + c8]);
            cp16(bBuf[buf] + (r * SM_STR + c8) * 2,
                 &Wc[(size_t)(bn0 + r) * KCAT + c * BKC + c8]);
        }
        CP_COMMIT();
    };

    issue(0);
    for (int c = 0; c < NCHUNK; ++c) {
        const int buf = c & 1;
        if (c + 1 < NCHUNK) { issue(c + 1); CP_WAIT(1); }
        else                { CP_WAIT(0); }
        __syncthreads();
#pragma unroll
        for (int ks = 0; ks < 4; ++ks) {
            uint32_t af[4][4];
#pragma unroll
            for (int mt = 0; mt < 4; mt++)
                ldsm4(af[mt], aBuf[buf] + aOff + (mt * 16 * SM_STR + ks * 16) * 2);
            uint32_t bf[2][4];
#pragma unroll
            for (int np = 0; np < 2; np++)
                ldsm4(bf[np], bBuf[buf] + bOff + (np * 16 * SM_STR + ks * 16) * 2);
#pragma unroll
            for (int mt = 0; mt < 4; mt++)
#pragma unroll
                for (int nt = 0; nt < 4; nt++)
                    mma16816(acc[mt][nt], af[mt],
                             bf[nt >> 1][(nt & 1) * 2],
                             bf[nt >> 1][(nt & 1) * 2 + 1]);
        }
        __syncthreads();
    }

    const int qr = L >> 2;
    const int qc = (L & 3) * 2;
#pragma unroll
    for (int mt = 0; mt < 4; mt++) {
        const int row0 = bm0 + wm * 64 + mt * 16 + qr;
#pragma unroll
        for (int nt = 0; nt < 4; nt++) {
            const int col = bn0 + wn * 32 + nt * 8 + qc;
            const float2 bv = *(const float2*)&bias[col];
            const float* cc = acc[mt][nt];
            const float a0 = cc[0] + bv.x, a1 = cc[1] + bv.y;
            const float a2 = cc[2] + bv.x, a3 = cc[3] + bv.y;
            if (mode == 0) {
                *(float2*)&C[(size_t)row0 * DM + col]       = make_float2(a0, a1);
                *(float2*)&C[(size_t)(row0 + 8) * DM + col] = make_float2(a2, a3);
            } else {
                const int b = row0 >> 12, s = row0 & 4095;
                const int h = col >> 6, d = col & 63;
                __half* o0 = Cc + ((size_t)(b * NHEAD + h) * SEQ + s) * DC2;
                __half* o1 = o0 + 8 * DC2;
                uint32_t lo0, lo1;
                const uint32_t hi0 = pack_hl(a0, a1, lo0);
                const uint32_t hi1 = pack_hl(a2, a3, lo1);
                *(uint32_t*)&o0[d]      = hi0;
                *(uint32_t*)&o0[64 + d] = (mode == 1) ? lo0 : hi0;
                *(uint32_t*)&o1[d]      = hi1;
                *(uint32_t*)&o1[64 + d] = (mode == 1) ? lo1 : hi1;
            }
        }
    }
}

// ===========================================================================
// Tensor-core flash attention (2-seg QK, 1-pass fp16 PV) — unchanged from R14.
// CTA: 128 q-rows x one (b,h); 8 warps; k-tiles of 64; 2 CTAs/SM.
// Smem: Qs[128][136] | Ks[2][64][136] | Vts[2][64][72] | msk[2][64]
// ===========================================================================
#define QS_STR  136
#define VT_STR  72
#define KBUF    17408
#define VBUF    9216
#define AS_Q    0
#define AS_K    34816
#define AS_V    69632
#define AS_M    88064
#define AS_TOT  88576

__global__ void __launch_bounds__(256, 2)
attn_tc_kernel(const int* __restrict__ mask)
{
    extern __shared__ char sm[];
    const uint32_t sb = smem_u32(sm);
    const int tid = threadIdx.x;
    const int wid = tid >> 5;
    const int L   = tid & 31;
    const int qt  = gridDim.x - 1 - blockIdx.x;   // heavy tiles first
    const int h   = blockIdx.y;
    const int b   = blockIdx.z;
    const int q0  = qt * 128;
    const int nkt = 2 * (qt + 1);

    const __half* Qc = g_Qc + (size_t)(b * NHEAD + h) * SEQ * DC2;
    const __half* Kc = g_Kc + (size_t)(b * NHEAD + h) * SEQ * DC2;
    const __half* Vt = g_Vt + (size_t)(b * NHEAD + h) * 64 * SEQ;
    const int* mrow_g = mask + b * SEQ;

    // Prologue: Q tile (2048 x 16B) + stages 0,1.
#pragma unroll
    for (int t = 0; t < 8; t++) {
        const int u = tid + t * 256;
        const int r = u >> 4, c = u & 15;
        cp16(sb + AS_Q + (r * QS_STR + c * 8) * 2,
             Qc + (size_t)(q0 + r) * DC2 + c * 8);
    }
    auto issueKV = [&](int i) {
        const uint32_t kb = sb + AS_K + (i & 1) * KBUF;
        const uint32_t vb = sb + AS_V + (i & 1) * VBUF;
#pragma unroll
        for (int t = 0; t < 4; t++) {
            const int u = tid + t * 256;          // 1024 units
            const int r = u >> 4, c = u & 15;
            cp16(kb + (r * QS_STR + c * 8) * 2,
                 Kc + (size_t)(i * 64 + r) * DC2 + c * 8);
        }
#pragma unroll
        for (int t = 0; t < 2; t++) {
            const int u = tid + t * 256;          // 512 units
            const int r = u >> 3, c = u & 7;
            cp16(vb + (r * VT_STR + c * 8) * 2,
                 Vt + (size_t)r * SEQ + i * 64 + c * 8);
        }
        if (tid < 16)
            cp16(sb + AS_M + (i & 1) * 256 + tid * 16, mrow_g + i * 64 + tid * 4);
    };
    issueKV(0); CP_COMMIT();
    issueKV(1); CP_COMMIT();

    // Frag address components (same mapping as tc_gemm, validated).
    const int aRow = (L & 7) + ((L >> 3) & 1) * 8;
    const int aK   = ((L >> 4) & 1) * 8;
    const int bRow = (L & 7) + ((L >> 4) & 1) * 8;
    const int bK   = ((L >> 3) & 1) * 8;
    const uint32_t aBase = sb + AS_Q + ((wid * 16 + aRow) * QS_STR + aK) * 2;
    const int lr  = L >> 2;
    const int lc2 = (L & 3) * 2;
    const int r0  = q0 + wid * 16 + lr;

    float sO[8][4];
#pragma unroll
    for (int nd = 0; nd < 8; nd++)
#pragma unroll
        for (int i = 0; i < 4; i++) sO[nd][i] = 0.f;
    float m[2] = { -INFINITY, -INFINITY };
    float l[2] = { 0.f, 0.f };

    for (int kt = 0; kt < nkt; ++kt) {
        const int buf = kt & 1;
        const int k0  = kt * 64;
        CP_WAIT(1);
        __syncthreads();

        const uint32_t kBase = sb + AS_K + buf * KBUF + (bRow * QS_STR + bK) * 2;
        const uint32_t vBase = sb + AS_V + buf * VBUF + (bRow * VT_STR + bK) * 2;
        const int* msk = (const int*)(sm + AS_M + buf * 256);

        // ---- S = [Qhi|Qlo] . [Khi|Khi]^T over d=128 ----
        float sS[8][4];
#pragma unroll
        for (int nt = 0; nt < 8; nt++)
#pragma unroll
            for (int i = 0; i < 4; i++) sS[nt][i] = 0.f;
#pragma unroll
        for (int ks = 0; ks < 8; ++ks) {
            uint32_t af[4];
            ldsm4(af, aBase + ks * 32);
            uint32_t bf[4][4];
#pragma unroll
            for (int np = 0; np < 4; np++)
                ldsm4(bf[np], kBase + (np * 16 * QS_STR + ks * 16) * 2);
#pragma unroll
            for (int nt = 0; nt < 8; nt++)
                mma16816(sS[nt], af,
                         bf[nt >> 1][(nt & 1) * 2],
                         bf[nt >> 1][(nt & 1) * 2 + 1]);
        }

        // ---- scale + masks ----
        const bool dg = (kt + 2 >= nkt);
#pragma unroll
        for (int nt = 0; nt < 8; nt++) {
            const int cr = nt * 8 + lc2;
            const int cg = k0 + cr;
            const int m0 = msk[cr], m1 = msk[cr + 1];
            float v0 = sS[nt][0] * 0.125f, v1 = sS[nt][1] * 0.125f;
            float v2 = sS[nt][2] * 0.125f, v3 = sS[nt][3] * 0.125f;
            if (m0 == 0) { v0 = NEGINF; v2 = NEGINF; }
            if (m1 == 0) { v1 = NEGINF; v3 = NEGINF; }
            if (dg) {
                if (cg > r0)         v0 = NEGINF;
                if (cg + 1 > r0)     v1 = NEGINF;
                if (cg > r0 + 8)     v2 = NEGINF;
                if (cg + 1 > r0 + 8) v3 = NEGINF;
            }
            sS[nt][0] = v0; sS[nt][1] = v1; sS[nt][2] = v2; sS[nt][3] = v3;
        }

        // ---- online softmax (rows owned by 4-lane groups) ----
#pragma unroll
        for (int i = 0; i < 2; i++) {
            float rm = -INFINITY;
#pragma unroll
            for (int nt = 0; nt < 8; nt++)
                rm = fmaxf(rm, fmaxf(sS[nt][i * 2], sS[nt][i * 2 + 1]));
            rm = fmaxf(rm, __shfl_xor_sync(0xffffffffu, rm, 1));
            rm = fmaxf(rm, __shfl_xor_sync(0xffffffffu, rm, 2));
            const float mn   = fmaxf(m[i], rm);
            const float corr = __expf(m[i] - mn);
            float rs = 0.f;
#pragma unroll
            for (int nt = 0; nt < 8; nt++) {
                sS[nt][i * 2]     = __expf(sS[nt][i * 2] - mn);
                sS[nt][i * 2 + 1] = __expf(sS[nt][i * 2 + 1] - mn);
                rs += sS[nt][i * 2] + sS[nt][i * 2 + 1];
            }
            rs += __shfl_xor_sync(0xffffffffu, rs, 1);
            rs += __shfl_xor_sync(0xffffffffu, rs, 2);
            l[i] = l[i] * corr + rs;
            m[i] = mn;
#pragma unroll
            for (int nd = 0; nd < 8; nd++) {
                sO[nd][i * 2]     *= corr;
                sO[nd][i * 2 + 1] *= corr;
            }
        }

        // ---- O += fp16(P).Vhi  (1-pass; acc frags reused as PV A-frags) ----
#pragma unroll
        for (int t = 0; t < 4; t++) {
            uint32_t ah[4];
            ah[0] = pack2(sS[2 * t][0],     sS[2 * t][1]);
            ah[1] = pack2(sS[2 * t][2],     sS[2 * t][3]);
            ah[2] = pack2(sS[2 * t + 1][0], sS[2 * t + 1][1]);
            ah[3] = pack2(sS[2 * t + 1][2], sS[2 * t + 1][3]);
            uint32_t bv[4][4];
#pragma unroll
            for (int np = 0; np < 4; np++)
                ldsm4(bv[np], vBase + (np * 16 * VT_STR + t * 16) * 2);
#pragma unroll
            for (int nd = 0; nd < 8; nd++)
                mma16816(sO[nd], ah, bv[nd >> 1][(nd & 1) * 2],
                         bv[nd >> 1][(nd & 1) * 2 + 1]);
        }

        __syncthreads();
        if (kt + 2 < nkt) issueKV(kt + 2);
        CP_COMMIT();
    }

    // ---- epilogue: normalize, write g_A[row][h*64 + d] ----
#pragma unroll
    for (int i = 0; i < 2; i++) {
        const float inv = 1.f / l[i];
        float* dst = g_A + ((size_t)b * SEQ + r0 + i * 8) * DM + h * DKH;
#pragma unroll
        for (int nd = 0; nd < 8; nd++)
            *(float2*)&dst[nd * 8 + lc2] =
                make_float2(sO[nd][i * 2] * inv, sO[nd][i * 2 + 1] * inv);
    }
}

// ===========================================================================
// Launch
// ===========================================================================
extern "C" void kernel_launch(void* const* d_in, const int* in_sizes, int n_in,
                              void* d_out, int out_size)
{
    const float* query = (const float*)d_in[0];
    const float* key   = (const float*)d_in[1];
    const float* value = (const float*)d_in[2];
    const int*   mask  = (const int*)  d_in[3];
    const float* Wq    = (const float*)d_in[4];
    const float* bq    = (const float*)d_in[5];
    const float* Wk    = (const float*)d_in[6];
    const float* bk    = (const float*)d_in[7];
    const float* Wv    = (const float*)d_in[8];
    const float* bv    = (const float*)d_in[9];
    const float* Wo    = (const float*)d_in[10];
    const float* bo    = (const float*)d_in[11];
    float* out = (float*)d_out;

    float *Vb, *Ab;
    __half *Xcat, *Wcat, *Qcp, *Kcp;
    cudaGetSymbolAddress((void**)&Vb, g_V);
    cudaGetSymbolAddress((void**)&Ab, g_A);
    cudaGetSymbolAddress((void**)&Xcat, g_Xcat);
    cudaGetSymbolAddress((void**)&Wcat, g_Wcat);
    cudaGetSymbolAddress((void**)&Qcp, g_Qc);
    cudaGetSymbolAddress((void**)&Kcp, g_Kc);

    cudaFuncSetAttribute(tc_gemm_kernel,
                         cudaFuncAttributeMaxDynamicSharedMemorySize, GS_TOTAL);
    cudaFuncSetAttribute(attn_tc_kernel,
                         cudaFuncAttributeMaxDynamicSharedMemorySize, AS_TOT);

    const int convX_blocks = (MROWS * (DM / 4) + 255) / 256;  // 6144
    const int convW_blocks = (DM * (DM / 4) + 255) / 256;     // 576
    const dim3 ggrid(MROWS / 128, DM / 128);                  // (64, 6)

    // Q projection -> g_Qc directly (split [hi|lo])
    conv_fp16_kernel<<<convX_blocks, 256>>>(query, Xcat, MROWS);
    conv_fp16_kernel<<<convW_blocks, 256>>>(Wq, Wcat, DM);
    tc_gemm_kernel<<<ggrid, 256, GS_TOTAL>>>(Xcat, Wcat, bq, nullptr, Qcp, 1);
    // K projection -> g_Kc directly ([hi|hi])
    conv_fp16_kernel<<<convX_blocks, 256>>>(key, Xcat, MROWS);
    conv_fp16_kernel<<<convW_blocks, 256>>>(Wk, Wcat, DM);
    tc_gemm_kernel<<<ggrid, 256, GS_TOTAL>>>(Xcat, Wcat, bk, nullptr, Kcp, 2);
    // V projection -> fp32 g_V, then transpose/convert (hi only)
    conv_fp16_kernel<<<convX_blocks, 256>>>(value, Xcat, MROWS);
    conv_fp16_kernel<<<convW_blocks, 256>>>(Wv, Wcat, DM);
    tc_gemm_kernel<<<ggrid, 256, GS_TOTAL>>>(Xcat, Wcat, bv, Vb, nullptr, 0);
    conv_v_kernel<<<dim3(SEQ / 64, NHEAD, BATCH), 256>>>();

    // Tensor-core flash attention
    attn_tc_kernel<<<dim3(SEQ / 128, NHEAD, BATCH), 256, AS_TOT>>>(mask);

    // Output projection
    conv_fp16_kernel<<<convX_blocks, 256>>>(Ab, Xcat, MROWS);
    conv_fp16_kernel<<<convW_blocks, 256>>>(Wo, Wcat, DM);
    tc_gemm_kernel<<<ggrid, 256, GS_TOTAL>>>(Xcat, Wcat, bo, out, nullptr, 0);
}